// round 1
// baseline (speedup 1.0000x reference)
#include <cuda_runtime.h>
#include <math.h>

#define NL   4      // layers
#define NB   4      // batch
#define SEQ  2048
#define DM   256
#define NH   8
#define DH   32
#define DF   512
#define MR   (NB*SEQ)   // 8192 rows

#define NEGF (-3.402823466e38f)

// ---------------- scratch (static __device__, no allocation) ----------------
__device__ float g_wqkv[NL*3*DM*DM];             // repacked QKV weights [n][m][d][h*32+e]
__device__ float g_qkv [3*(size_t)MR*DM];        // q,k,v  each [B*L, 256]
__device__ float g_obuf[(size_t)MR*DM];          // attention output [B*L, 256]
__device__ float g_xc  [(size_t)MR*DM];          // running hidden state
__device__ float g_ff  [(size_t)MR*DF];          // FF intermediate

// ---------------- weight repack: Wq/Wk/Wv [n][h][d][e] -> [n][m][d][h*32+e] --
__global__ void prep_w_kernel(const float* __restrict__ Wq,
                              const float* __restrict__ Wk,
                              const float* __restrict__ Wv) {
    int i = blockIdx.x * blockDim.x + threadIdx.x;
    const int total = NL*NH*DM*DH;     // 262144
    if (i >= total) return;
    int e = i & (DH-1);
    int d = (i / DH) & (DM-1);
    int h = (i / (DH*DM)) & (NH-1);
    int n = i / (DH*DM*NH);
    int dst = ((n*3)*DM + d)*DM + h*DH + e;
    g_wqkv[dst]             = Wq[i];
    g_wqkv[dst +   DM*DM]   = Wk[i];
    g_wqkv[dst + 2*DM*DM]   = Wv[i];
}

// ---------------- fused SGEMM -----------------------------------------------
// C[M,N] = epilogue( sum_k A[M,K]*B[K,N] )
// mode 0: plain, B and C offset by blockIdx.z (QKV triple GEMM)
// mode 1: C = (acc + res)*0.5
// mode 2: C = gelu_exact(acc + bias[n])
// mode 3: C = (acc + bias[n] + res)*0.5
#define BM 64
#define BN 64
#define BK 16
#define TM 4
#define TN 4

__device__ __forceinline__ float gelu_exact(float x) {
    return 0.5f * x * (1.0f + erff(x * 0.70710678118654752440f));
}

__global__ __launch_bounds__(256)
void gemm_fused(const float* __restrict__ A, const float* __restrict__ B,
                const float* __restrict__ bias, const float* __restrict__ res,
                float* __restrict__ C, int M, int N, int K, int mode) {
    __shared__ float As[BK][BM + 4];   // +4 pad: keeps 16B alignment, cuts STS conflicts
    __shared__ float Bs[BK][BN];

    if (mode == 0) {
        B += (size_t)blockIdx.z * K * N;
        C += (size_t)blockIdx.z * (size_t)M * N;
    }
    int bm = blockIdx.y * BM;
    int bn = blockIdx.x * BN;
    int tid = threadIdx.x;

    float acc[TM][TN];
    #pragma unroll
    for (int i = 0; i < TM; i++)
        #pragma unroll
        for (int j = 0; j < TN; j++) acc[i][j] = 0.0f;

    // A tile load mapping: 64 rows x 16 cols = 256 float4, one per thread
    int a_row  = tid >> 2;            // 0..63
    int a_col4 = (tid & 3) << 2;      // 0,4,8,12
    // B tile load mapping: 16 rows x 64 cols = 256 float4, one per thread
    int b_row  = tid >> 4;            // 0..15
    int b_col4 = (tid & 15) << 2;     // 0..60

    const float* Aptr = A + (size_t)(bm + a_row) * K + a_col4;
    const float* Bptr = B + (size_t)b_row * N + bn + b_col4;

    int tm0 = (tid >> 4) * TM;
    int tn0 = (tid & 15) * TN;

    for (int k0 = 0; k0 < K; k0 += BK) {
        float4 av = *(const float4*)(Aptr + k0);
        As[a_col4 + 0][a_row] = av.x;
        As[a_col4 + 1][a_row] = av.y;
        As[a_col4 + 2][a_row] = av.z;
        As[a_col4 + 3][a_row] = av.w;
        *(float4*)&Bs[b_row][b_col4] = *(const float4*)(Bptr + (size_t)k0 * N);
        __syncthreads();

        #pragma unroll
        for (int k = 0; k < BK; k++) {
            float ar[TM], br[TN];
            *(float4*)ar = *(const float4*)&As[k][tm0];
            *(float4*)br = *(const float4*)&Bs[k][tn0];
            #pragma unroll
            for (int i = 0; i < TM; i++)
                #pragma unroll
                for (int j = 0; j < TN; j++)
                    acc[i][j] = fmaf(ar[i], br[j], acc[i][j]);
        }
        __syncthreads();
    }

    // epilogue (float4 stores)
    float4 bb = make_float4(0.f, 0.f, 0.f, 0.f);
    if (mode == 2 || mode == 3) bb = *(const float4*)(bias + bn + tn0);

    #pragma unroll
    for (int i = 0; i < TM; i++) {
        size_t off = (size_t)(bm + tm0 + i) * N + bn + tn0;
        float4 v = make_float4(acc[i][0], acc[i][1], acc[i][2], acc[i][3]);
        if (mode == 1) {
            float4 r = *(const float4*)(res + off);
            v.x = (v.x + r.x) * 0.5f; v.y = (v.y + r.y) * 0.5f;
            v.z = (v.z + r.z) * 0.5f; v.w = (v.w + r.w) * 0.5f;
        } else if (mode == 2) {
            v.x = gelu_exact(v.x + bb.x); v.y = gelu_exact(v.y + bb.y);
            v.z = gelu_exact(v.z + bb.z); v.w = gelu_exact(v.w + bb.w);
        } else if (mode == 3) {
            float4 r = *(const float4*)(res + off);
            v.x = (v.x + bb.x + r.x) * 0.5f; v.y = (v.y + bb.y + r.y) * 0.5f;
            v.z = (v.z + bb.z + r.z) * 0.5f; v.w = (v.w + bb.w + r.w) * 0.5f;
        }
        *(float4*)(C + off) = v;
    }
}

// ---------------- flash attention -------------------------------------------
// q,k,v stored as [B*L, 256] with head h occupying cols [h*32, h*32+32).
// One thread per query row; K/V staged in smem tiles of KT keys.
#define QB 128
#define KT 64

__global__ __launch_bounds__(QB)
void attn_kernel(const float* __restrict__ gq, const float* __restrict__ gk,
                 const float* __restrict__ gv, const float* __restrict__ gmask,
                 float* __restrict__ go) {
    __shared__ float Ks[KT][DH];
    __shared__ float Vs[KT][DH];
    __shared__ float Ms[KT];

    int bh = blockIdx.y;
    int b  = bh / NH;
    int h  = bh % NH;
    int ql = blockIdx.x * QB + threadIdx.x;

    const float* qrow = gq + ((size_t)b * SEQ + ql) * DM + h * DH;
    float4 q4[8];
    #pragma unroll
    for (int i = 0; i < 8; i++) q4[i] = ((const float4*)qrow)[i];

    float mq = gmask[b * SEQ + ql];

    float4 o4[8];
    #pragma unroll
    for (int i = 0; i < 8; i++) o4[i] = make_float4(0.f, 0.f, 0.f, 0.f);
    float mmax = NEGF;
    float ssum = 0.0f;

    for (int j0 = 0; j0 < SEQ; j0 += KT) {
        __syncthreads();
        // stage KT rows of K and V (512 float4 each / 128 threads = 4 each)
        #pragma unroll
        for (int t = 0; t < 4; t++) {
            int idx = threadIdx.x + t * QB;        // 0..511
            int r   = idx >> 3;                    // 0..63
            int c4  = idx & 7;                     // 0..7
            size_t base = ((size_t)b * SEQ + j0 + r) * DM + h * DH;
            ((float4*)Ks[r])[c4] = ((const float4*)(gk + base))[c4];
            ((float4*)Vs[r])[c4] = ((const float4*)(gv + base))[c4];
        }
        if (threadIdx.x < KT) Ms[threadIdx.x] = gmask[b * SEQ + j0 + threadIdx.x];
        __syncthreads();

        for (int j = 0; j < KT; j++) {
            float s = 0.0f;
            const float4* kr = (const float4*)Ks[j];
            #pragma unroll
            for (int d = 0; d < 8; d++) {
                float4 kv = kr[d];
                s = fmaf(q4[d].x, kv.x, s);
                s = fmaf(q4[d].y, kv.y, s);
                s = fmaf(q4[d].z, kv.z, s);
                s = fmaf(q4[d].w, kv.w, s);
            }
            s += (1.0f - mq * Ms[j]) * NEGF;

            float p;
            if (s > mmax) {
                float scale = __expf(mmax - s);
                ssum *= scale;
                #pragma unroll
                for (int d = 0; d < 8; d++) {
                    o4[d].x *= scale; o4[d].y *= scale;
                    o4[d].z *= scale; o4[d].w *= scale;
                }
                mmax = s;
                p = 1.0f;
            } else {
                p = __expf(s - mmax);
            }
            ssum += p;

            const float4* vr = (const float4*)Vs[j];
            #pragma unroll
            for (int d = 0; d < 8; d++) {
                float4 vv = vr[d];
                o4[d].x = fmaf(p, vv.x, o4[d].x);
                o4[d].y = fmaf(p, vv.y, o4[d].y);
                o4[d].z = fmaf(p, vv.z, o4[d].z);
                o4[d].w = fmaf(p, vv.w, o4[d].w);
            }
        }
    }

    float inv = 1.0f / ssum;
    float* orow = go + ((size_t)b * SEQ + ql) * DM + h * DH;
    #pragma unroll
    for (int d = 0; d < 8; d++) {
        float4 t = o4[d];
        t.x *= inv; t.y *= inv; t.z *= inv; t.w *= inv;
        ((float4*)orow)[d] = t;
    }
}

// ---------------- launch ----------------------------------------------------
extern "C" void kernel_launch(void* const* d_in, const int* in_sizes, int n_in,
                              void* d_out, int out_size) {
    const float* x    = (const float*)d_in[0];
    const float* mask = (const float*)d_in[1];
    const float* Wq   = (const float*)d_in[2];
    const float* Wk   = (const float*)d_in[3];
    const float* Wv   = (const float*)d_in[4];
    const float* Wo   = (const float*)d_in[5];
    const float* W1   = (const float*)d_in[6];
    const float* b1   = (const float*)d_in[7];
    const float* W2   = (const float*)d_in[8];
    const float* b2   = (const float*)d_in[9];
    float* out = (float*)d_out;

    float *wqkv_p, *qkv_p, *o_p, *xc_p, *ff_p;
    cudaGetSymbolAddress((void**)&wqkv_p, g_wqkv);
    cudaGetSymbolAddress((void**)&qkv_p,  g_qkv);
    cudaGetSymbolAddress((void**)&o_p,    g_obuf);
    cudaGetSymbolAddress((void**)&xc_p,   g_xc);
    cudaGetSymbolAddress((void**)&ff_p,   g_ff);

    prep_w_kernel<<<(NL*NH*DM*DH + 255) / 256, 256>>>(Wq, Wk, Wv);

    const size_t QKV_STRIDE = (size_t)MR * DM;   // 2M floats

    for (int n = 0; n < NL; n++) {
        const float* xin = (n == 0) ? x : xc_p;

        // QKV: 3 GEMMs [8192,256] = [8192,256] @ [256,256]
        gemm_fused<<<dim3(DM/BN, MR/BM, 3), 256>>>(
            xin, wqkv_p + (size_t)n * 3 * DM * DM, nullptr, nullptr,
            qkv_p, MR, DM, DM, 0);

        // attention
        attn_kernel<<<dim3(SEQ/QB, NB*NH), QB>>>(
            qkv_p, qkv_p + QKV_STRIDE, qkv_p + 2 * QKV_STRIDE, mask, o_p);

        // xc = (o @ Wo + xin) * 0.5
        gemm_fused<<<dim3(DM/BN, MR/BM, 1), 256>>>(
            o_p, Wo + (size_t)n * DM * DM, nullptr, xin,
            xc_p, MR, DM, DM, 1);

        // ff = gelu(xc @ W1 + b1)
        gemm_fused<<<dim3(DF/BN, MR/BM, 1), 256>>>(
            xc_p, W1 + (size_t)n * DM * DF, b1 + (size_t)n * DF, nullptr,
            ff_p, MR, DF, DM, 2);

        // xc = (ff @ W2 + b2 + xc) * 0.5   (last layer writes d_out)
        float* dst = (n == NL - 1) ? out : xc_p;
        gemm_fused<<<dim3(DM/BN, MR/BM, 1), 256>>>(
            ff_p, W2 + (size_t)n * DF * DM, b2 + (size_t)n * DM, xc_p,
            dst, MR, DM, DF, 3);
    }
}

// round 2
// speedup vs baseline: 1.1024x; 1.1024x over previous
#include <cuda_runtime.h>
#include <math.h>

#define NL   4
#define NB   4
#define SEQ  2048
#define DM   256
#define NH   8
#define DH   32
#define DF   512
#define MR   (NB*SEQ)

#define NEGF (-3.402823466e38f)

typedef unsigned long long u64;

// ---------------- packed f32x2 helpers (sm_103a FFMA2 path) -----------------
__device__ __forceinline__ u64 dup2(float x) {
    u64 r; asm("mov.b64 %0, {%1,%1};" : "=l"(r) : "f"(x)); return r;
}
__device__ __forceinline__ void unpack2(u64 a, float& x, float& y) {
    asm("mov.b64 {%0,%1}, %2;" : "=f"(x), "=f"(y) : "l"(a));
}
__device__ __forceinline__ void fma2(u64& d, u64 a, u64 b) {
    asm("fma.rn.f32x2 %0, %1, %2, %0;" : "+l"(d) : "l"(a), "l"(b));
}
__device__ __forceinline__ u64 mul2(u64 a, u64 b) {
    u64 r; asm("mul.rn.f32x2 %0, %1, %2;" : "=l"(r) : "l"(a), "l"(b)); return r;
}
__device__ __forceinline__ u64 add2(u64 a, u64 b) {
    u64 r; asm("add.rn.f32x2 %0, %1, %2;" : "=l"(r) : "l"(a), "l"(b)); return r;
}

// ---------------- scratch ----------------------------------------------------
__device__ float g_wqkv[NL*3*DM*DM];
__device__ float g_qkv [3*(size_t)MR*DM];
__device__ float g_obuf[(size_t)MR*DM];
__device__ float g_xc  [(size_t)MR*DM];
__device__ float g_ff  [(size_t)MR*DF];

// ---------------- weight repack ----------------------------------------------
__global__ void prep_w_kernel(const float* __restrict__ Wq,
                              const float* __restrict__ Wk,
                              const float* __restrict__ Wv) {
    int i = blockIdx.x * blockDim.x + threadIdx.x;
    const int total = NL*NH*DM*DH;
    if (i >= total) return;
    int e = i & (DH-1);
    int d = (i / DH) & (DM-1);
    int h = (i / (DH*DM)) & (NH-1);
    int n = i / (DH*DM*NH);
    int dst = ((n*3)*DM + d)*DM + h*DH + e;
    g_wqkv[dst]           = Wq[i];
    g_wqkv[dst +   DM*DM] = Wk[i];
    g_wqkv[dst + 2*DM*DM] = Wv[i];
}

// ---------------- fused SGEMM (FFMA2, double-buffered) -----------------------
// mode 0: plain (B,C offset by blockIdx.z)   mode 1: (acc+res)*0.5
// mode 2: gelu(acc+bias)                     mode 3: (acc+bias+res)*0.5
#define BM 128
#define BN 64
#define BK 16

__device__ __forceinline__ float gelu_exact(float x) {
    return 0.5f * x * (1.0f + erff(x * 0.70710678118654752440f));
}

__device__ __forceinline__ void epi_store(float* C, size_t off, float v[4],
                                          const float4& bb, const float* res, int mode) {
    float4 o;
    if (mode == 1) {
        float4 r = *(const float4*)(res + off);
        o.x = (v[0] + r.x)*0.5f; o.y = (v[1] + r.y)*0.5f;
        o.z = (v[2] + r.z)*0.5f; o.w = (v[3] + r.w)*0.5f;
    } else if (mode == 2) {
        o.x = gelu_exact(v[0] + bb.x); o.y = gelu_exact(v[1] + bb.y);
        o.z = gelu_exact(v[2] + bb.z); o.w = gelu_exact(v[3] + bb.w);
    } else if (mode == 3) {
        float4 r = *(const float4*)(res + off);
        o.x = (v[0] + bb.x + r.x)*0.5f; o.y = (v[1] + bb.y + r.y)*0.5f;
        o.z = (v[2] + bb.z + r.z)*0.5f; o.w = (v[3] + bb.w + r.w)*0.5f;
    } else {
        o.x = v[0]; o.y = v[1]; o.z = v[2]; o.w = v[3];
    }
    *(float4*)(C + off) = o;
}

__global__ __launch_bounds__(256, 2)
void gemm_fused(const float* __restrict__ A, const float* __restrict__ B,
                const float* __restrict__ bias, const float* __restrict__ res,
                float* __restrict__ C, int M, int N, int K, int mode) {
    __shared__ float As[2][BK][BM];   // transposed: As[k][m]
    __shared__ float Bs[2][BK][BN];

    if (mode == 0) {
        B += (size_t)blockIdx.z * K * N;
        C += (size_t)blockIdx.z * (size_t)M * N;
    }
    int bm = blockIdx.y * BM;
    int bn = blockIdx.x * BN;
    int tid = threadIdx.x;

    // global load mapping
    int ar  = tid >> 2;            // 0..63 (two rows: ar, ar+64)
    int ac4 = (tid & 3) << 2;      // 0,4,8,12
    int brow = tid >> 4;           // 0..15
    int bc4  = (tid & 15) << 2;    // 0..60

    const float* Ap0 = A + (size_t)(bm + ar) * K + ac4;
    const float* Ap1 = Ap0 + (size_t)64 * K;
    const float* Bp  = B + (size_t)brow * N + bn + bc4;

    // compute mapping: rows [tm0, tm0+8), cols [tn0, tn0+4)
    int tm0 = (tid >> 4) << 3;
    int tn0 = (tid & 15) << 2;

    u64 acc[4][4] = {};   // acc[i][j] = (row tm0+2i, row tm0+2i+1) x col tn0+j

    int nt = K / BK;
    float4 fa0 = *(const float4*)Ap0;
    float4 fa1 = *(const float4*)Ap1;
    float4 fb  = *(const float4*)Bp;
    #pragma unroll
    for (int j = 0; j < 4; j++) {
        As[0][ac4+j][ar]    = ((float*)&fa0)[j];
        As[0][ac4+j][ar+64] = ((float*)&fa1)[j];
    }
    *(float4*)&Bs[0][brow][bc4] = fb;
    __syncthreads();

    int buf = 0;
    for (int t = 0; t < nt; t++) {
        if (t + 1 < nt) {
            fa0 = *(const float4*)(Ap0 + (t+1)*BK);
            fa1 = *(const float4*)(Ap1 + (t+1)*BK);
            fb  = *(const float4*)(Bp + (size_t)(t+1)*BK*N);
        }
        #pragma unroll
        for (int k = 0; k < BK; k++) {
            ulonglong2 am0 = *(const ulonglong2*)&As[buf][k][tm0];
            ulonglong2 am1 = *(const ulonglong2*)&As[buf][k][tm0+4];
            float4 bv = *(const float4*)&Bs[buf][k][tn0];
            u64 a0 = am0.x, a1 = am0.y, a2 = am1.x, a3 = am1.y;
            u64 b0 = dup2(bv.x), b1 = dup2(bv.y), b2 = dup2(bv.z), b3 = dup2(bv.w);
            fma2(acc[0][0], a0, b0); fma2(acc[0][1], a0, b1);
            fma2(acc[0][2], a0, b2); fma2(acc[0][3], a0, b3);
            fma2(acc[1][0], a1, b0); fma2(acc[1][1], a1, b1);
            fma2(acc[1][2], a1, b2); fma2(acc[1][3], a1, b3);
            fma2(acc[2][0], a2, b0); fma2(acc[2][1], a2, b1);
            fma2(acc[2][2], a2, b2); fma2(acc[2][3], a2, b3);
            fma2(acc[3][0], a3, b0); fma2(acc[3][1], a3, b1);
            fma2(acc[3][2], a3, b2); fma2(acc[3][3], a3, b3);
        }
        if (t + 1 < nt) {
            int nb = buf ^ 1;
            #pragma unroll
            for (int j = 0; j < 4; j++) {
                As[nb][ac4+j][ar]    = ((float*)&fa0)[j];
                As[nb][ac4+j][ar+64] = ((float*)&fa1)[j];
            }
            *(float4*)&Bs[nb][brow][bc4] = fb;
            __syncthreads();
            buf = nb;
        }
    }

    float4 bb = make_float4(0.f, 0.f, 0.f, 0.f);
    if (mode == 2 || mode == 3) bb = *(const float4*)(bias + bn + tn0);

    #pragma unroll
    for (int i = 0; i < 4; i++) {
        float v0[4], v1[4];
        #pragma unroll
        for (int j = 0; j < 4; j++) unpack2(acc[i][j], v0[j], v1[j]);
        size_t off0 = (size_t)(bm + tm0 + 2*i)     * N + bn + tn0;
        size_t off1 = (size_t)(bm + tm0 + 2*i + 1) * N + bn + tn0;
        epi_store(C, off0, v0, bb, res, mode);
        epi_store(C, off1, v1, bb, res, mode);
    }
}

// ---------------- flash attention (FFMA2) ------------------------------------
#define QB 128
#define KT 64

__global__ __launch_bounds__(QB)
void attn_kernel(const float* __restrict__ gq, const float* __restrict__ gk,
                 const float* __restrict__ gv, const float* __restrict__ gmask,
                 float* __restrict__ go) {
    __shared__ float Ks[KT][DH];
    __shared__ float Vs[KT][DH];
    __shared__ float Ms[KT];

    int bh = blockIdx.y;
    int b  = bh / NH;
    int h  = bh % NH;
    int ql = blockIdx.x * QB + threadIdx.x;

    const float* qrow = gq + ((size_t)b * SEQ + ql) * DM + h * DH;
    u64 q2[16];
    {
        const ulonglong2* qp = (const ulonglong2*)qrow;
        #pragma unroll
        for (int i = 0; i < 8; i++) {
            ulonglong2 t = qp[i];
            q2[2*i]   = t.x;
            q2[2*i+1] = t.y;
        }
    }
    float mq = gmask[b * SEQ + ql];

    u64 o2[16] = {};
    float mmax = NEGF;
    float ssum = 0.0f;

    for (int j0 = 0; j0 < SEQ; j0 += KT) {
        __syncthreads();
        #pragma unroll
        for (int t = 0; t < 4; t++) {
            int idx = threadIdx.x + t * QB;
            int r   = idx >> 3;
            int c4  = idx & 7;
            size_t base = ((size_t)b * SEQ + j0 + r) * DM + h * DH;
            ((float4*)Ks[r])[c4] = ((const float4*)(gk + base))[c4];
            ((float4*)Vs[r])[c4] = ((const float4*)(gv + base))[c4];
        }
        if (threadIdx.x < KT) Ms[threadIdx.x] = gmask[b * SEQ + j0 + threadIdx.x];
        __syncthreads();

        for (int j = 0; j < KT; j++) {
            const ulonglong2* kr = (const ulonglong2*)Ks[j];
            ulonglong2 k0 = kr[0], k1 = kr[1], k2 = kr[2], k3 = kr[3];
            ulonglong2 k4 = kr[4], k5 = kr[5], k6 = kr[6], k7 = kr[7];
            u64 s0 = mul2(q2[0], k0.x);
            u64 s1 = mul2(q2[1], k0.y);
            u64 s2 = mul2(q2[2], k1.x);
            u64 s3 = mul2(q2[3], k1.y);
            fma2(s0, q2[4],  k2.x); fma2(s1, q2[5],  k2.y);
            fma2(s2, q2[6],  k3.x); fma2(s3, q2[7],  k3.y);
            fma2(s0, q2[8],  k4.x); fma2(s1, q2[9],  k4.y);
            fma2(s2, q2[10], k5.x); fma2(s3, q2[11], k5.y);
            fma2(s0, q2[12], k6.x); fma2(s1, q2[13], k6.y);
            fma2(s2, q2[14], k7.x); fma2(s3, q2[15], k7.y);
            u64 sA = add2(add2(s0, s1), add2(s2, s3));
            float sl, sh; unpack2(sA, sl, sh);
            float s = sl + sh;
            s = fmaf(1.0f - mq * Ms[j], NEGF, s);

            float p;
            if (s > mmax) {
                float scale = __expf(mmax - s);
                ssum *= scale;
                u64 sc = dup2(scale);
                #pragma unroll
                for (int d = 0; d < 16; d++) o2[d] = mul2(o2[d], sc);
                mmax = s;
                p = 1.0f;
            } else {
                p = __expf(s - mmax);
            }
            ssum += p;

            u64 pd = dup2(p);
            const ulonglong2* vr = (const ulonglong2*)Vs[j];
            #pragma unroll
            for (int d = 0; d < 8; d++) {
                ulonglong2 vv = vr[d];
                fma2(o2[2*d],   pd, vv.x);
                fma2(o2[2*d+1], pd, vv.y);
            }
        }
    }

    u64 inv = dup2(1.0f / ssum);
    ulonglong2* orow = (ulonglong2*)(go + ((size_t)b * SEQ + ql) * DM + h * DH);
    #pragma unroll
    for (int i = 0; i < 8; i++) {
        ulonglong2 t;
        t.x = mul2(o2[2*i],   inv);
        t.y = mul2(o2[2*i+1], inv);
        orow[i] = t;
    }
}

// ---------------- launch ------------------------------------------------------
extern "C" void kernel_launch(void* const* d_in, const int* in_sizes, int n_in,
                              void* d_out, int out_size) {
    const float* x    = (const float*)d_in[0];
    const float* mask = (const float*)d_in[1];
    const float* Wq   = (const float*)d_in[2];
    const float* Wk   = (const float*)d_in[3];
    const float* Wv   = (const float*)d_in[4];
    const float* Wo   = (const float*)d_in[5];
    const float* W1   = (const float*)d_in[6];
    const float* b1   = (const float*)d_in[7];
    const float* W2   = (const float*)d_in[8];
    const float* b2   = (const float*)d_in[9];
    float* out = (float*)d_out;

    float *wqkv_p, *qkv_p, *o_p, *xc_p, *ff_p;
    cudaGetSymbolAddress((void**)&wqkv_p, g_wqkv);
    cudaGetSymbolAddress((void**)&qkv_p,  g_qkv);
    cudaGetSymbolAddress((void**)&o_p,    g_obuf);
    cudaGetSymbolAddress((void**)&xc_p,   g_xc);
    cudaGetSymbolAddress((void**)&ff_p,   g_ff);

    prep_w_kernel<<<(NL*NH*DM*DH + 255) / 256, 256>>>(Wq, Wk, Wv);

    const size_t QKV_STRIDE = (size_t)MR * DM;

    for (int n = 0; n < NL; n++) {
        const float* xin = (n == 0) ? x : xc_p;

        gemm_fused<<<dim3(DM/BN, MR/BM, 3), 256>>>(
            xin, wqkv_p + (size_t)n * 3 * DM * DM, nullptr, nullptr,
            qkv_p, MR, DM, DM, 0);

        attn_kernel<<<dim3(SEQ/QB, NB*NH), QB>>>(
            qkv_p, qkv_p + QKV_STRIDE, qkv_p + 2 * QKV_STRIDE, mask, o_p);

        gemm_fused<<<dim3(DM/BN, MR/BM, 1), 256>>>(
            o_p, Wo + (size_t)n * DM * DM, nullptr, xin,
            xc_p, MR, DM, DM, 1);

        gemm_fused<<<dim3(DF/BN, MR/BM, 1), 256>>>(
            xc_p, W1 + (size_t)n * DM * DF, b1 + (size_t)n * DF, nullptr,
            ff_p, MR, DF, DM, 2);

        float* dst = (n == NL - 1) ? out : xc_p;
        gemm_fused<<<dim3(DM/BN, MR/BM, 1), 256>>>(
            ff_p, W2 + (size_t)n * DF * DM, b2 + (size_t)n * DM, xc_p,
            dst, MR, DM, DF, 3);
    }
}

// round 4
// speedup vs baseline: 1.6941x; 1.5368x over previous
#include <cuda_runtime.h>
#include <math.h>
#include <stdint.h>

#define NL   4
#define NB   4
#define SEQ  2048
#define DM   256
#define NH   8
#define DH   32
#define DF   512
#define MR   (NB*SEQ)

#define NEGF (-3.402823466e38f)

typedef unsigned long long u64;

// ================= packed f32x2 helpers =================
__device__ __forceinline__ u64 dup2(float x) {
    u64 r; asm("mov.b64 %0, {%1,%1};" : "=l"(r) : "f"(x)); return r;
}
__device__ __forceinline__ void unpack2(u64 a, float& x, float& y) {
    asm("mov.b64 {%0,%1}, %2;" : "=f"(x), "=f"(y) : "l"(a));
}
__device__ __forceinline__ void fma2(u64& d, u64 a, u64 b) {
    asm("fma.rn.f32x2 %0, %1, %2, %0;" : "+l"(d) : "l"(a), "l"(b));
}

// ================= mma.sync helpers =================
__device__ __forceinline__ uint32_t f2tf32(float x) {
    uint32_t r; asm("cvt.rna.tf32.f32 %0, %1;" : "=r"(r) : "f"(x)); return r;
}
// pack two f32 -> bf16x2 (first arg in low 16 bits)
__device__ __forceinline__ uint32_t pack_bf16x2(float lo, float hi) {
    uint32_t r; asm("cvt.rn.bf16x2.f32 %0, %1, %2;" : "=r"(r) : "f"(hi), "f"(lo)); return r;
}
__device__ __forceinline__ void mma_tf32(float* c, const uint32_t* a, const uint32_t* b) {
    asm volatile(
        "mma.sync.aligned.m16n8k8.row.col.f32.tf32.tf32.f32 "
        "{%0,%1,%2,%3},{%4,%5,%6,%7},{%8,%9},{%0,%1,%2,%3};"
        : "+f"(c[0]), "+f"(c[1]), "+f"(c[2]), "+f"(c[3])
        : "r"(a[0]), "r"(a[1]), "r"(a[2]), "r"(a[3]), "r"(b[0]), "r"(b[1]));
}
__device__ __forceinline__ void mma_bf16(float* c, const uint32_t* a, const uint32_t* b) {
    asm volatile(
        "mma.sync.aligned.m16n8k16.row.col.f32.bf16.bf16.f32 "
        "{%0,%1,%2,%3},{%4,%5,%6,%7},{%8,%9},{%0,%1,%2,%3};"
        : "+f"(c[0]), "+f"(c[1]), "+f"(c[2]), "+f"(c[3])
        : "r"(a[0]), "r"(a[1]), "r"(a[2]), "r"(a[3]), "r"(b[0]), "r"(b[1]));
}

// ================= scratch =================
__device__ float g_wqkv[NL*3*DM*DM];
__device__ float g_qkv [3*(size_t)MR*DM];
__device__ float g_vt  [(size_t)MR*DM];     // V transposed: [b][h][e][l]
__device__ float g_obuf[(size_t)MR*DM];
__device__ float g_xc  [(size_t)MR*DM];
__device__ float g_ff  [(size_t)MR*DF];

// ================= weight repack =================
__global__ void prep_w_kernel(const float* __restrict__ Wq,
                              const float* __restrict__ Wk,
                              const float* __restrict__ Wv) {
    int i = blockIdx.x * blockDim.x + threadIdx.x;
    const int total = NL*NH*DM*DH;
    if (i >= total) return;
    int e = i & (DH-1);
    int d = (i / DH) & (DM-1);
    int h = (i / (DH*DM)) & (NH-1);
    int n = i / (DH*DM*NH);
    int dst = ((n*3)*DM + d)*DM + h*DH + e;
    g_wqkv[dst]           = Wq[i];
    g_wqkv[dst +   DM*DM] = Wk[i];
    g_wqkv[dst + 2*DM*DM] = Wv[i];
}

// ================= V transpose =================
__global__ void transpose_v(const float* __restrict__ v, float* __restrict__ vt) {
    __shared__ float tl[32][33];
    int bh = blockIdx.y;
    int b = bh >> 3, h = bh & 7;
    int l0 = blockIdx.x * 32;
    #pragma unroll
    for (int k = 0; k < 4; k++) {
        int l = l0 + threadIdx.y + k*8;
        tl[threadIdx.y + k*8][threadIdx.x] = v[((size_t)b*SEQ + l)*DM + h*32 + threadIdx.x];
    }
    __syncthreads();
    #pragma unroll
    for (int k = 0; k < 4; k++) {
        int e = threadIdx.y + k*8;
        vt[((size_t)bh*32 + e)*SEQ + l0 + threadIdx.x] = tl[threadIdx.x][e];
    }
}

// ================= fused SGEMM (FFMA2, double-buffered) =================
#define BM 128
#define BN 64
#define BK 16

__device__ __forceinline__ float gelu_exact(float x) {
    return 0.5f * x * (1.0f + erff(x * 0.70710678118654752440f));
}

__device__ __forceinline__ void epi_store(float* C, size_t off, float v[4],
                                          const float4& bb, const float* res, int mode) {
    float4 o;
    if (mode == 1) {
        float4 r = *(const float4*)(res + off);
        o.x = (v[0] + r.x)*0.5f; o.y = (v[1] + r.y)*0.5f;
        o.z = (v[2] + r.z)*0.5f; o.w = (v[3] + r.w)*0.5f;
    } else if (mode == 2) {
        o.x = gelu_exact(v[0] + bb.x); o.y = gelu_exact(v[1] + bb.y);
        o.z = gelu_exact(v[2] + bb.z); o.w = gelu_exact(v[3] + bb.w);
    } else if (mode == 3) {
        float4 r = *(const float4*)(res + off);
        o.x = (v[0] + bb.x + r.x)*0.5f; o.y = (v[1] + bb.y + r.y)*0.5f;
        o.z = (v[2] + bb.z + r.z)*0.5f; o.w = (v[3] + bb.w + r.w)*0.5f;
    } else {
        o.x = v[0]; o.y = v[1]; o.z = v[2]; o.w = v[3];
    }
    *(float4*)(C + off) = o;
}

__global__ __launch_bounds__(256, 2)
void gemm_fused(const float* __restrict__ A, const float* __restrict__ B,
                const float* __restrict__ bias, const float* __restrict__ res,
                float* __restrict__ C, int M, int N, int K, int mode) {
    __shared__ float As[2][BK][BM];
    __shared__ float Bs[2][BK][BN];

    if (mode == 0) {
        B += (size_t)blockIdx.z * K * N;
        C += (size_t)blockIdx.z * (size_t)M * N;
    }
    int bm = blockIdx.y * BM;
    int bn = blockIdx.x * BN;
    int tid = threadIdx.x;

    int ar  = tid >> 2;
    int ac4 = (tid & 3) << 2;
    int brow = tid >> 4;
    int bc4  = (tid & 15) << 2;

    const float* Ap0 = A + (size_t)(bm + ar) * K + ac4;
    const float* Ap1 = Ap0 + (size_t)64 * K;
    const float* Bp  = B + (size_t)brow * N + bn + bc4;

    int tm0 = (tid >> 4) << 3;
    int tn0 = (tid & 15) << 2;

    u64 acc[4][4] = {};

    int nt = K / BK;
    float4 fa0 = *(const float4*)Ap0;
    float4 fa1 = *(const float4*)Ap1;
    float4 fb  = *(const float4*)Bp;
    #pragma unroll
    for (int j = 0; j < 4; j++) {
        As[0][ac4+j][ar]    = ((float*)&fa0)[j];
        As[0][ac4+j][ar+64] = ((float*)&fa1)[j];
    }
    *(float4*)&Bs[0][brow][bc4] = fb;
    __syncthreads();

    int buf = 0;
    for (int t = 0; t < nt; t++) {
        if (t + 1 < nt) {
            fa0 = *(const float4*)(Ap0 + (t+1)*BK);
            fa1 = *(const float4*)(Ap1 + (t+1)*BK);
            fb  = *(const float4*)(Bp + (size_t)(t+1)*BK*N);
        }
        #pragma unroll
        for (int k = 0; k < BK; k++) {
            ulonglong2 am0 = *(const ulonglong2*)&As[buf][k][tm0];
            ulonglong2 am1 = *(const ulonglong2*)&As[buf][k][tm0+4];
            float4 bv = *(const float4*)&Bs[buf][k][tn0];
            u64 a0 = am0.x, a1 = am0.y, a2 = am1.x, a3 = am1.y;
            u64 b0 = dup2(bv.x), b1 = dup2(bv.y), b2 = dup2(bv.z), b3 = dup2(bv.w);
            fma2(acc[0][0], a0, b0); fma2(acc[0][1], a0, b1);
            fma2(acc[0][2], a0, b2); fma2(acc[0][3], a0, b3);
            fma2(acc[1][0], a1, b0); fma2(acc[1][1], a1, b1);
            fma2(acc[1][2], a1, b2); fma2(acc[1][3], a1, b3);
            fma2(acc[2][0], a2, b0); fma2(acc[2][1], a2, b1);
            fma2(acc[2][2], a2, b2); fma2(acc[2][3], a2, b3);
            fma2(acc[3][0], a3, b0); fma2(acc[3][1], a3, b1);
            fma2(acc[3][2], a3, b2); fma2(acc[3][3], a3, b3);
        }
        if (t + 1 < nt) {
            int nb = buf ^ 1;
            #pragma unroll
            for (int j = 0; j < 4; j++) {
                As[nb][ac4+j][ar]    = ((float*)&fa0)[j];
                As[nb][ac4+j][ar+64] = ((float*)&fa1)[j];
            }
            *(float4*)&Bs[nb][brow][bc4] = fb;
            __syncthreads();
            buf = nb;
        }
    }

    float4 bb = make_float4(0.f, 0.f, 0.f, 0.f);
    if (mode == 2 || mode == 3) bb = *(const float4*)(bias + bn + tn0);

    #pragma unroll
    for (int i = 0; i < 4; i++) {
        float v0[4], v1[4];
        #pragma unroll
        for (int j = 0; j < 4; j++) unpack2(acc[i][j], v0[j], v1[j]);
        size_t off0 = (size_t)(bm + tm0 + 2*i)     * N + bn + tn0;
        size_t off1 = (size_t)(bm + tm0 + 2*i + 1) * N + bn + tn0;
        epi_store(C, off0, v0, bb, res, mode);
        epi_store(C, off1, v1, bb, res, mode);
    }
}

// ================= warp-MMA flash attention =================
// CTA: 128 queries x one (b,h). 4 warps x 32 rows (2 m16 frags).
// QK: 3xTF32 m16n8k8 (hi/lo split).  PV: bf16 3-term m16n8k16.
// KT=32 keys per iteration.
#define KT 32

__global__ __launch_bounds__(128, 2)
void attn_mma(const float* __restrict__ gq, const float* __restrict__ gk,
              const float* __restrict__ gvt, const float* __restrict__ gmask,
              float* __restrict__ go) {
    __shared__ float    Ksh[2][DH][33];   // [hi/lo][dim][key]
    __shared__ uint32_t Vsh[2][DH][20];   // [hi/lo][dim][key-pair] bf16x2
    __shared__ float    sMask[KT];

    int tid  = threadIdx.x;
    int warp = tid >> 5;
    int lane = tid & 31;
    int g    = lane >> 2;     // 0..7
    int j    = lane & 3;      // 0..3
    int bh   = blockIdx.y;
    int b    = bh >> 3, h = bh & 7;
    int q0   = blockIdx.x * 128 + warp * 32;

    // ---- load Q fragments (tf32 hi/lo), loop-invariant ----
    uint32_t qhi[2][4][4], qlo[2][4][4];
    #pragma unroll
    for (int mt = 0; mt < 2; mt++) {
        #pragma unroll
        for (int ks = 0; ks < 4; ks++) {
            #pragma unroll
            for (int idx = 0; idx < 4; idx++) {
                int row = q0 + mt*16 + g + (idx & 1)*8;
                int dim = ks*8 + j + (idx >> 1)*4;
                float v = gq[((size_t)b*SEQ + row)*DM + h*DH + dim];
                uint32_t hi = f2tf32(v);
                qhi[mt][ks][idx] = hi;
                qlo[mt][ks][idx] = f2tf32(v - __uint_as_float(hi));
            }
        }
    }
    float mqv[2][2];
    #pragma unroll
    for (int mt = 0; mt < 2; mt++) {
        mqv[mt][0] = gmask[b*SEQ + q0 + mt*16 + g];
        mqv[mt][1] = gmask[b*SEQ + q0 + mt*16 + g + 8];
    }

    float mrow[2][2], lrow[2][2], ofr[2][4][4];
    #pragma unroll
    for (int mt = 0; mt < 2; mt++) {
        mrow[mt][0] = NEGF; mrow[mt][1] = NEGF;
        lrow[mt][0] = 0.f;  lrow[mt][1] = 0.f;
        #pragma unroll
        for (int nd = 0; nd < 4; nd++)
            #pragma unroll
            for (int r = 0; r < 4; r++) ofr[mt][nd][r] = 0.f;
    }

    for (int it = 0; it < SEQ/KT; it++) {
        int j0 = it * KT;
        __syncthreads();

        // ---- stage K (tf32 hi/lo, transposed [dim][key]) ----
        {
            int key = tid & 31;
            int db  = (tid >> 5) * 8;
            const float4* kr = (const float4*)(gk + ((size_t)b*SEQ + j0 + key)*DM + h*DH + db);
            float4 v0 = kr[0], v1 = kr[1];
            float vv[8] = {v0.x, v0.y, v0.z, v0.w, v1.x, v1.y, v1.z, v1.w};
            #pragma unroll
            for (int d = 0; d < 8; d++) {
                uint32_t hi = f2tf32(vv[d]);
                Ksh[0][db + d][key] = __uint_as_float(hi);
                Ksh[1][db + d][key] = __uint_as_float(f2tf32(vv[d] - __uint_as_float(hi)));
            }
        }
        // ---- stage V (bf16x2 hi/lo, [dim][pair]) ----
        {
            int dim = tid >> 2;
            int kg  = tid & 3;
            const float4* vr = (const float4*)(gvt + ((size_t)bh*DH + dim)*SEQ + j0 + kg*8);
            float4 v0 = vr[0], v1 = vr[1];
            float vv[8] = {v0.x, v0.y, v0.z, v0.w, v1.x, v1.y, v1.z, v1.w};
            #pragma unroll
            for (int p = 0; p < 4; p++) {
                float a = vv[2*p], c = vv[2*p+1];
                uint32_t hp = pack_bf16x2(a, c);
                float ra = a - __uint_as_float(hp << 16);
                float rc = c - __uint_as_float(hp & 0xffff0000u);
                Vsh[0][dim][kg*4 + p] = hp;
                Vsh[1][dim][kg*4 + p] = pack_bf16x2(ra, rc);
            }
        }
        if (tid < KT) sMask[tid] = gmask[b*SEQ + j0 + tid];
        __syncthreads();

        // ---- S = Q K^T  (3xTF32) ----
        float sfr[2][4][4];
        #pragma unroll
        for (int mt = 0; mt < 2; mt++)
            #pragma unroll
            for (int n = 0; n < 4; n++)
                #pragma unroll
                for (int r = 0; r < 4; r++) sfr[mt][n][r] = 0.f;

        #pragma unroll
        for (int n = 0; n < 4; n++) {
            #pragma unroll
            for (int ks = 0; ks < 4; ks++) {
                uint32_t bhi[2], blo[2];
                bhi[0] = __float_as_uint(Ksh[0][ks*8 + j][n*8 + g]);
                bhi[1] = __float_as_uint(Ksh[0][ks*8 + j + 4][n*8 + g]);
                blo[0] = __float_as_uint(Ksh[1][ks*8 + j][n*8 + g]);
                blo[1] = __float_as_uint(Ksh[1][ks*8 + j + 4][n*8 + g]);
                #pragma unroll
                for (int mt = 0; mt < 2; mt++) {
                    mma_tf32(sfr[mt][n], qhi[mt][ks], bhi);
                    mma_tf32(sfr[mt][n], qlo[mt][ks], bhi);
                    mma_tf32(sfr[mt][n], qhi[mt][ks], blo);
                }
            }
        }

        // ---- softmax + P fragments ----
        uint32_t phr0[2][4], phr1[2][4], plr0[2][4], plr1[2][4];
        #pragma unroll
        for (int mt = 0; mt < 2; mt++) {
            float mq0 = mqv[mt][0], mq1 = mqv[mt][1];
            float rmax0 = NEGF, rmax1 = NEGF;
            #pragma unroll
            for (int n = 0; n < 4; n++) {
                float mk0 = sMask[n*8 + 2*j];
                float mk1 = sMask[n*8 + 2*j + 1];
                float s0 = fmaf(fmaf(-mq0, mk0, 1.0f), NEGF, sfr[mt][n][0]);
                float s1 = fmaf(fmaf(-mq0, mk1, 1.0f), NEGF, sfr[mt][n][1]);
                float s2 = fmaf(fmaf(-mq1, mk0, 1.0f), NEGF, sfr[mt][n][2]);
                float s3 = fmaf(fmaf(-mq1, mk1, 1.0f), NEGF, sfr[mt][n][3]);
                sfr[mt][n][0] = s0; sfr[mt][n][1] = s1;
                sfr[mt][n][2] = s2; sfr[mt][n][3] = s3;
                rmax0 = fmaxf(rmax0, fmaxf(s0, s1));
                rmax1 = fmaxf(rmax1, fmaxf(s2, s3));
            }
            rmax0 = fmaxf(rmax0, __shfl_xor_sync(0xffffffffu, rmax0, 1));
            rmax0 = fmaxf(rmax0, __shfl_xor_sync(0xffffffffu, rmax0, 2));
            rmax1 = fmaxf(rmax1, __shfl_xor_sync(0xffffffffu, rmax1, 1));
            rmax1 = fmaxf(rmax1, __shfl_xor_sync(0xffffffffu, rmax1, 2));

            float nm0 = fmaxf(mrow[mt][0], rmax0);
            float nm1 = fmaxf(mrow[mt][1], rmax1);
            float sc0 = __expf(mrow[mt][0] - nm0);
            float sc1 = __expf(mrow[mt][1] - nm1);
            mrow[mt][0] = nm0; mrow[mt][1] = nm1;
            lrow[mt][0] *= sc0; lrow[mt][1] *= sc1;
            #pragma unroll
            for (int nd = 0; nd < 4; nd++) {
                ofr[mt][nd][0] *= sc0; ofr[mt][nd][1] *= sc0;
                ofr[mt][nd][2] *= sc1; ofr[mt][nd][3] *= sc1;
            }
            float ls0 = 0.f, ls1 = 0.f;
            #pragma unroll
            for (int n = 0; n < 4; n++) {
                float p0 = __expf(sfr[mt][n][0] - nm0);
                float p1 = __expf(sfr[mt][n][1] - nm0);
                float p2 = __expf(sfr[mt][n][2] - nm1);
                float p3 = __expf(sfr[mt][n][3] - nm1);
                ls0 += p0 + p1; ls1 += p2 + p3;
                uint32_t h01 = pack_bf16x2(p0, p1);
                uint32_t h23 = pack_bf16x2(p2, p3);
                phr0[mt][n] = h01;
                phr1[mt][n] = h23;
                plr0[mt][n] = pack_bf16x2(p0 - __uint_as_float(h01 << 16),
                                          p1 - __uint_as_float(h01 & 0xffff0000u));
                plr1[mt][n] = pack_bf16x2(p2 - __uint_as_float(h23 << 16),
                                          p3 - __uint_as_float(h23 & 0xffff0000u));
            }
            lrow[mt][0] += ls0; lrow[mt][1] += ls1;
        }

        // ---- O += P V  (bf16 3-term) ----
        #pragma unroll
        for (int nd = 0; nd < 4; nd++) {
            #pragma unroll
            for (int k2 = 0; k2 < 2; k2++) {
                uint32_t bhi[2], blo[2];
                bhi[0] = Vsh[0][nd*8 + g][k2*8 + j];
                bhi[1] = Vsh[0][nd*8 + g][k2*8 + j + 4];
                blo[0] = Vsh[1][nd*8 + g][k2*8 + j];
                blo[1] = Vsh[1][nd*8 + g][k2*8 + j + 4];
                #pragma unroll
                for (int mt = 0; mt < 2; mt++) {
                    uint32_t ahi[4] = {phr0[mt][2*k2], phr1[mt][2*k2],
                                       phr0[mt][2*k2+1], phr1[mt][2*k2+1]};
                    uint32_t alo[4] = {plr0[mt][2*k2], plr1[mt][2*k2],
                                       plr0[mt][2*k2+1], plr1[mt][2*k2+1]};
                    mma_bf16(ofr[mt][nd], ahi, bhi);
                    mma_bf16(ofr[mt][nd], ahi, blo);
                    mma_bf16(ofr[mt][nd], alo, bhi);
                }
            }
        }
    }

    // ---- epilogue ----
    #pragma unroll
    for (int mt = 0; mt < 2; mt++) {
        float l0 = lrow[mt][0], l1 = lrow[mt][1];
        l0 += __shfl_xor_sync(0xffffffffu, l0, 1);
        l0 += __shfl_xor_sync(0xffffffffu, l0, 2);
        l1 += __shfl_xor_sync(0xffffffffu, l1, 1);
        l1 += __shfl_xor_sync(0xffffffffu, l1, 2);
        float inv0 = 1.0f / l0, inv1 = 1.0f / l1;
        int r0 = q0 + mt*16 + g;
        #pragma unroll
        for (int nd = 0; nd < 4; nd++) {
            int col = h*DH + nd*8 + 2*j;
            float2 v0 = make_float2(ofr[mt][nd][0]*inv0, ofr[mt][nd][1]*inv0);
            float2 v1 = make_float2(ofr[mt][nd][2]*inv1, ofr[mt][nd][3]*inv1);
            *(float2*)(go + ((size_t)b*SEQ + r0)*DM + col)     = v0;
            *(float2*)(go + ((size_t)b*SEQ + r0 + 8)*DM + col) = v1;
        }
    }
}

// ================= launch =================
extern "C" void kernel_launch(void* const* d_in, const int* in_sizes, int n_in,
                              void* d_out, int out_size) {
    const float* x    = (const float*)d_in[0];
    const float* mask = (const float*)d_in[1];
    const float* Wq   = (const float*)d_in[2];
    const float* Wk   = (const float*)d_in[3];
    const float* Wv   = (const float*)d_in[4];
    const float* Wo   = (const float*)d_in[5];
    const float* W1   = (const float*)d_in[6];
    const float* b1   = (const float*)d_in[7];
    const float* W2   = (const float*)d_in[8];
    const float* b2   = (const float*)d_in[9];
    float* out = (float*)d_out;

    float *wqkv_p, *qkv_p, *vt_p, *o_p, *xc_p, *ff_p;
    cudaGetSymbolAddress((void**)&wqkv_p, g_wqkv);
    cudaGetSymbolAddress((void**)&qkv_p,  g_qkv);
    cudaGetSymbolAddress((void**)&vt_p,   g_vt);
    cudaGetSymbolAddress((void**)&o_p,    g_obuf);
    cudaGetSymbolAddress((void**)&xc_p,   g_xc);
    cudaGetSymbolAddress((void**)&ff_p,   g_ff);

    prep_w_kernel<<<(NL*NH*DM*DH + 255) / 256, 256>>>(Wq, Wk, Wv);

    const size_t QKV_STRIDE = (size_t)MR * DM;

    for (int n = 0; n < NL; n++) {
        const float* xin = (n == 0) ? x : xc_p;

        gemm_fused<<<dim3(DM/BN, MR/BM, 3), 256>>>(
            xin, wqkv_p + (size_t)n * 3 * DM * DM, nullptr, nullptr,
            qkv_p, MR, DM, DM, 0);

        transpose_v<<<dim3(SEQ/32, NB*NH), dim3(32, 8)>>>(
            qkv_p + 2*QKV_STRIDE, vt_p);

        attn_mma<<<dim3(SEQ/128, NB*NH), 128>>>(
            qkv_p, qkv_p + QKV_STRIDE, vt_p, mask, o_p);

        gemm_fused<<<dim3(DM/BN, MR/BM, 1), 256>>>(
            o_p, Wo + (size_t)n * DM * DM, nullptr, xin,
            xc_p, MR, DM, DM, 1);

        gemm_fused<<<dim3(DF/BN, MR/BM, 1), 256>>>(
            xc_p, W1 + (size_t)n * DM * DF, b1 + (size_t)n * DF, nullptr,
            ff_p, MR, DF, DM, 2);

        float* dst = (n == NL - 1) ? out : xc_p;
        gemm_fused<<<dim3(DM/BN, MR/BM, 1), 256>>>(
            ff_p, W2 + (size_t)n * DF * DM, b2 + (size_t)n * DM, xc_p,
            dst, MR, DM, DF, 3);
    }
}

// round 5
// speedup vs baseline: 2.0972x; 1.2380x over previous
#include <cuda_runtime.h>
#include <math.h>
#include <stdint.h>

#define NL   4
#define NB   4
#define SEQ  2048
#define DM   256
#define NH   8
#define DH   32
#define DF   512
#define MR   (NB*SEQ)

#define NEGF (-3.402823466e38f)

typedef unsigned long long u64;

// ================= packed f32x2 helpers =================
__device__ __forceinline__ u64 dup2(float x) {
    u64 r; asm("mov.b64 %0, {%1,%1};" : "=l"(r) : "f"(x)); return r;
}
__device__ __forceinline__ void unpack2(u64 a, float& x, float& y) {
    asm("mov.b64 {%0,%1}, %2;" : "=f"(x), "=f"(y) : "l"(a));
}
__device__ __forceinline__ void fma2(u64& d, u64 a, u64 b) {
    asm("fma.rn.f32x2 %0, %1, %2, %0;" : "+l"(d) : "l"(a), "l"(b));
}

// ================= mma helpers =================
// pack two f32 -> bf16x2 (first arg in low 16 bits)
__device__ __forceinline__ uint32_t pack_bf16x2(float lo, float hi) {
    uint32_t r; asm("cvt.rn.bf16x2.f32 %0, %1, %2;" : "=r"(r) : "f"(hi), "f"(lo)); return r;
}
__device__ __forceinline__ float bf_low(uint32_t p)  { return __uint_as_float(p << 16); }
__device__ __forceinline__ float bf_high(uint32_t p) { return __uint_as_float(p & 0xffff0000u); }

__device__ __forceinline__ void mma_bf16(float* c, const uint32_t* a, const uint32_t* b) {
    asm volatile(
        "mma.sync.aligned.m16n8k16.row.col.f32.bf16.bf16.f32 "
        "{%0,%1,%2,%3},{%4,%5,%6,%7},{%8,%9},{%0,%1,%2,%3};"
        : "+f"(c[0]), "+f"(c[1]), "+f"(c[2]), "+f"(c[3])
        : "r"(a[0]), "r"(a[1]), "r"(a[2]), "r"(a[3]), "r"(b[0]), "r"(b[1]));
}

// ================= scratch =================
__device__ float g_wqkv[NL*3*DM*DM];
__device__ float g_qkv [3*(size_t)MR*DM];
__device__ float g_vt  [(size_t)MR*DM];     // V transposed: [b][h][e][l]
__device__ float g_obuf[(size_t)MR*DM];
__device__ float g_xc  [(size_t)MR*DM];
__device__ float g_ff  [(size_t)MR*DF];

// ================= weight repack =================
__global__ void prep_w_kernel(const float* __restrict__ Wq,
                              const float* __restrict__ Wk,
                              const float* __restrict__ Wv) {
    int i = blockIdx.x * blockDim.x + threadIdx.x;
    const int total = NL*NH*DM*DH;
    if (i >= total) return;
    int e = i & (DH-1);
    int d = (i / DH) & (DM-1);
    int h = (i / (DH*DM)) & (NH-1);
    int n = i / (DH*DM*NH);
    int dst = ((n*3)*DM + d)*DM + h*DH + e;
    g_wqkv[dst]           = Wq[i];
    g_wqkv[dst +   DM*DM] = Wk[i];
    g_wqkv[dst + 2*DM*DM] = Wv[i];
}

// ================= V transpose =================
__global__ void transpose_v(const float* __restrict__ v, float* __restrict__ vt) {
    __shared__ float tl[32][33];
    int bh = blockIdx.y;
    int b = bh >> 3, h = bh & 7;
    int l0 = blockIdx.x * 32;
    #pragma unroll
    for (int k = 0; k < 4; k++) {
        int l = l0 + threadIdx.y + k*8;
        tl[threadIdx.y + k*8][threadIdx.x] = v[((size_t)b*SEQ + l)*DM + h*32 + threadIdx.x];
    }
    __syncthreads();
    #pragma unroll
    for (int k = 0; k < 4; k++) {
        int e = threadIdx.y + k*8;
        vt[((size_t)bh*32 + e)*SEQ + l0 + threadIdx.x] = tl[threadIdx.x][e];
    }
}

// ================= fused SGEMM (FFMA2, double-buffered) =================
#define BM 128
#define BN 64
#define BK 16

__device__ __forceinline__ float gelu_exact(float x) {
    return 0.5f * x * (1.0f + erff(x * 0.70710678118654752440f));
}

__device__ __forceinline__ void epi_store(float* C, size_t off, float v[4],
                                          const float4& bb, const float* res, int mode) {
    float4 o;
    if (mode == 1) {
        float4 r = *(const float4*)(res + off);
        o.x = (v[0] + r.x)*0.5f; o.y = (v[1] + r.y)*0.5f;
        o.z = (v[2] + r.z)*0.5f; o.w = (v[3] + r.w)*0.5f;
    } else if (mode == 2) {
        o.x = gelu_exact(v[0] + bb.x); o.y = gelu_exact(v[1] + bb.y);
        o.z = gelu_exact(v[2] + bb.z); o.w = gelu_exact(v[3] + bb.w);
    } else if (mode == 3) {
        float4 r = *(const float4*)(res + off);
        o.x = (v[0] + bb.x + r.x)*0.5f; o.y = (v[1] + bb.y + r.y)*0.5f;
        o.z = (v[2] + bb.z + r.z)*0.5f; o.w = (v[3] + bb.w + r.w)*0.5f;
    } else {
        o.x = v[0]; o.y = v[1]; o.z = v[2]; o.w = v[3];
    }
    *(float4*)(C + off) = o;
}

__global__ __launch_bounds__(256, 2)
void gemm_fused(const float* __restrict__ A, const float* __restrict__ B,
                const float* __restrict__ bias, const float* __restrict__ res,
                float* __restrict__ C, int M, int N, int K, int mode) {
    __shared__ float As[2][BK][BM];
    __shared__ float Bs[2][BK][BN];

    if (mode == 0) {
        B += (size_t)blockIdx.z * K * N;
        C += (size_t)blockIdx.z * (size_t)M * N;
    }
    int bm = blockIdx.y * BM;
    int bn = blockIdx.x * BN;
    int tid = threadIdx.x;

    int ar  = tid >> 2;
    int ac4 = (tid & 3) << 2;
    int brow = tid >> 4;
    int bc4  = (tid & 15) << 2;

    const float* Ap0 = A + (size_t)(bm + ar) * K + ac4;
    const float* Ap1 = Ap0 + (size_t)64 * K;
    const float* Bp  = B + (size_t)brow * N + bn + bc4;

    int tm0 = (tid >> 4) << 3;
    int tn0 = (tid & 15) << 2;

    u64 acc[4][4] = {};

    int nt = K / BK;
    float4 fa0 = *(const float4*)Ap0;
    float4 fa1 = *(const float4*)Ap1;
    float4 fb  = *(const float4*)Bp;
    #pragma unroll
    for (int j = 0; j < 4; j++) {
        As[0][ac4+j][ar]    = ((float*)&fa0)[j];
        As[0][ac4+j][ar+64] = ((float*)&fa1)[j];
    }
    *(float4*)&Bs[0][brow][bc4] = fb;
    __syncthreads();

    int buf = 0;
    for (int t = 0; t < nt; t++) {
        if (t + 1 < nt) {
            fa0 = *(const float4*)(Ap0 + (t+1)*BK);
            fa1 = *(const float4*)(Ap1 + (t+1)*BK);
            fb  = *(const float4*)(Bp + (size_t)(t+1)*BK*N);
        }
        #pragma unroll
        for (int k = 0; k < BK; k++) {
            ulonglong2 am0 = *(const ulonglong2*)&As[buf][k][tm0];
            ulonglong2 am1 = *(const ulonglong2*)&As[buf][k][tm0+4];
            float4 bv = *(const float4*)&Bs[buf][k][tn0];
            u64 a0 = am0.x, a1 = am0.y, a2 = am1.x, a3 = am1.y;
            u64 b0 = dup2(bv.x), b1 = dup2(bv.y), b2 = dup2(bv.z), b3 = dup2(bv.w);
            fma2(acc[0][0], a0, b0); fma2(acc[0][1], a0, b1);
            fma2(acc[0][2], a0, b2); fma2(acc[0][3], a0, b3);
            fma2(acc[1][0], a1, b0); fma2(acc[1][1], a1, b1);
            fma2(acc[1][2], a1, b2); fma2(acc[1][3], a1, b3);
            fma2(acc[2][0], a2, b0); fma2(acc[2][1], a2, b1);
            fma2(acc[2][2], a2, b2); fma2(acc[2][3], a2, b3);
            fma2(acc[3][0], a3, b0); fma2(acc[3][1], a3, b1);
            fma2(acc[3][2], a3, b2); fma2(acc[3][3], a3, b3);
        }
        if (t + 1 < nt) {
            int nb = buf ^ 1;
            #pragma unroll
            for (int j = 0; j < 4; j++) {
                As[nb][ac4+j][ar]    = ((float*)&fa0)[j];
                As[nb][ac4+j][ar+64] = ((float*)&fa1)[j];
            }
            *(float4*)&Bs[nb][brow][bc4] = fb;
            __syncthreads();
            buf = nb;
        }
    }

    float4 bb = make_float4(0.f, 0.f, 0.f, 0.f);
    if (mode == 2 || mode == 3) bb = *(const float4*)(bias + bn + tn0);

    #pragma unroll
    for (int i = 0; i < 4; i++) {
        float v0[4], v1[4];
        #pragma unroll
        for (int j = 0; j < 4; j++) unpack2(acc[i][j], v0[j], v1[j]);
        size_t off0 = (size_t)(bm + tm0 + 2*i)     * N + bn + tn0;
        size_t off1 = (size_t)(bm + tm0 + 2*i + 1) * N + bn + tn0;
        epi_store(C, off0, v0, bb, res, mode);
        epi_store(C, off1, v1, bb, res, mode);
    }
}

// ================= warp-MMA flash attention (all-bf16 3-term, pipelined) ====
// CTA: 128 queries x one (b,h). 4 warps x 32 rows (2 m16 frags).
// QK: bf16 3-term m16n8k16 (hi/lo split, error ~1.4e-4 absolute on logits).
// PV: bf16 3-term m16n8k16.  KT=32 keys/iter, double-buffered smem, one sync/iter.
#define KT  32
#define NIT (SEQ/KT)

__global__ __launch_bounds__(128, 3)
void attn_mma(const float* __restrict__ gq, const float* __restrict__ gk,
              const float* __restrict__ gvt, const float* __restrict__ gmask,
              float* __restrict__ go) {
    __shared__ uint32_t Ksh[2][2][16][40];  // [buf][hi/lo][dim-pair][key] bf16x2
    __shared__ uint32_t Vsh[2][2][32][20];  // [buf][hi/lo][dim][key-pair] bf16x2
    __shared__ float    sMask[2][KT];

    int tid  = threadIdx.x;
    int warp = tid >> 5;
    int lane = tid & 31;
    int g    = lane >> 2;     // 0..7
    int j    = lane & 3;      // 0..3
    int bh   = blockIdx.y;
    int b    = bh >> 3, h = bh & 7;
    int q0   = blockIdx.x * 128 + warp * 32;

    // ---- Q fragments (bf16 hi/lo), loop-invariant ----
    uint32_t qh[2][2][4], ql[2][2][4];
    #pragma unroll
    for (int mt = 0; mt < 2; mt++) {
        #pragma unroll
        for (int rr = 0; rr < 2; rr++) {
            int row = q0 + mt*16 + g + rr*8;
            const float* qp = gq + ((size_t)b*SEQ + row)*DM + h*DH;
            #pragma unroll
            for (int u = 0; u < 4; u++) {
                float2 v = *(const float2*)(qp + u*8 + 2*j);
                uint32_t hp = pack_bf16x2(v.x, v.y);
                uint32_t lp = pack_bf16x2(v.x - bf_low(hp), v.y - bf_high(hp));
                qh[mt][u>>1][rr + 2*(u&1)] = hp;
                ql[mt][u>>1][rr + 2*(u&1)] = lp;
            }
        }
    }
    float mqv[2][2];
    #pragma unroll
    for (int mt = 0; mt < 2; mt++) {
        mqv[mt][0] = gmask[b*SEQ + q0 + mt*16 + g];
        mqv[mt][1] = gmask[b*SEQ + q0 + mt*16 + g + 8];
    }

    float mrow[2][2], lrow[2][2], ofr[2][4][4];
    #pragma unroll
    for (int mt = 0; mt < 2; mt++) {
        mrow[mt][0] = NEGF; mrow[mt][1] = NEGF;
        lrow[mt][0] = 0.f;  lrow[mt][1] = 0.f;
        #pragma unroll
        for (int nd = 0; nd < 4; nd++)
            #pragma unroll
            for (int r = 0; r < 4; r++) ofr[mt][nd][r] = 0.f;
    }

    // ---- producer bases ----
    int kkey = lane;
    int kdb  = warp * 8;          // 8 dims per warp
    int vdim = tid >> 2;
    int vkg  = tid & 3;
    const float* kbase = gk  + ((size_t)b*SEQ + kkey)*DM + h*DH + kdb;
    const float* vbase = gvt + ((size_t)bh*DH + vdim)*SEQ + vkg*8;
    const float* mbase = gmask + b*SEQ + tid;

    float4 ka, kb2, va, vb2; float ml = 0.f;
    ka  = *(const float4*)(kbase);
    kb2 = *(const float4*)(kbase + 4);
    va  = *(const float4*)(vbase);
    vb2 = *(const float4*)(vbase + 4);
    if (tid < KT) ml = *mbase;

    // ---- stage tile 0 into buf 0 ----
    {
        float kv[8] = {ka.x,ka.y,ka.z,ka.w,kb2.x,kb2.y,kb2.z,kb2.w};
        #pragma unroll
        for (int i = 0; i < 4; i++) {
            uint32_t hp = pack_bf16x2(kv[2*i], kv[2*i+1]);
            Ksh[0][0][(kdb>>1)+i][kkey] = hp;
            Ksh[0][1][(kdb>>1)+i][kkey] =
                pack_bf16x2(kv[2*i] - bf_low(hp), kv[2*i+1] - bf_high(hp));
        }
        float vv[8] = {va.x,va.y,va.z,va.w,vb2.x,vb2.y,vb2.z,vb2.w};
        #pragma unroll
        for (int p = 0; p < 4; p++) {
            uint32_t hp = pack_bf16x2(vv[2*p], vv[2*p+1]);
            Vsh[0][0][vdim][vkg*4+p] = hp;
            Vsh[0][1][vdim][vkg*4+p] =
                pack_bf16x2(vv[2*p] - bf_low(hp), vv[2*p+1] - bf_high(hp));
        }
        if (tid < KT) sMask[0][tid] = ml;
    }
    __syncthreads();

    for (int it = 0; it < NIT; it++) {
        int bufc = it & 1;
        // ---- prefetch next tile into registers (latency hidden by compute) --
        if (it + 1 < NIT) {
            const float* kp = kbase + (size_t)(it+1)*KT*DM;
            const float* vp = vbase + (it+1)*KT;
            ka  = *(const float4*)(kp);
            kb2 = *(const float4*)(kp + 4);
            va  = *(const float4*)(vp);
            vb2 = *(const float4*)(vp + 4);
            if (tid < KT) ml = mbase[(it+1)*KT];
        }

        // ---- S = Q K^T  (bf16 3-term) ----
        float sfr[2][4][4];
        #pragma unroll
        for (int mt = 0; mt < 2; mt++)
            #pragma unroll
            for (int n = 0; n < 4; n++)
                #pragma unroll
                for (int r = 0; r < 4; r++) sfr[mt][n][r] = 0.f;

        #pragma unroll
        for (int n = 0; n < 4; n++) {
            #pragma unroll
            for (int ks = 0; ks < 2; ks++) {
                uint32_t bhi[2], blo[2];
                bhi[0] = Ksh[bufc][0][ks*8 + j][n*8 + g];
                bhi[1] = Ksh[bufc][0][ks*8 + j + 4][n*8 + g];
                blo[0] = Ksh[bufc][1][ks*8 + j][n*8 + g];
                blo[1] = Ksh[bufc][1][ks*8 + j + 4][n*8 + g];
                #pragma unroll
                for (int mt = 0; mt < 2; mt++) {
                    mma_bf16(sfr[mt][n], qh[mt][ks], bhi);
                    mma_bf16(sfr[mt][n], ql[mt][ks], bhi);
                    mma_bf16(sfr[mt][n], qh[mt][ks], blo);
                }
            }
        }

        // ---- softmax + P fragments ----
        uint32_t phr0[2][4], phr1[2][4], plr0[2][4], plr1[2][4];
        #pragma unroll
        for (int mt = 0; mt < 2; mt++) {
            float mq0 = mqv[mt][0], mq1 = mqv[mt][1];
            float rmax0 = NEGF, rmax1 = NEGF;
            #pragma unroll
            for (int n = 0; n < 4; n++) {
                float mk0 = sMask[bufc][n*8 + 2*j];
                float mk1 = sMask[bufc][n*8 + 2*j + 1];
                float s0 = fmaf(fmaf(-mq0, mk0, 1.0f), NEGF, sfr[mt][n][0]);
                float s1 = fmaf(fmaf(-mq0, mk1, 1.0f), NEGF, sfr[mt][n][1]);
                float s2 = fmaf(fmaf(-mq1, mk0, 1.0f), NEGF, sfr[mt][n][2]);
                float s3 = fmaf(fmaf(-mq1, mk1, 1.0f), NEGF, sfr[mt][n][3]);
                sfr[mt][n][0] = s0; sfr[mt][n][1] = s1;
                sfr[mt][n][2] = s2; sfr[mt][n][3] = s3;
                rmax0 = fmaxf(rmax0, fmaxf(s0, s1));
                rmax1 = fmaxf(rmax1, fmaxf(s2, s3));
            }
            rmax0 = fmaxf(rmax0, __shfl_xor_sync(0xffffffffu, rmax0, 1));
            rmax0 = fmaxf(rmax0, __shfl_xor_sync(0xffffffffu, rmax0, 2));
            rmax1 = fmaxf(rmax1, __shfl_xor_sync(0xffffffffu, rmax1, 1));
            rmax1 = fmaxf(rmax1, __shfl_xor_sync(0xffffffffu, rmax1, 2));

            float nm0 = fmaxf(mrow[mt][0], rmax0);
            float nm1 = fmaxf(mrow[mt][1], rmax1);
            float sc0 = __expf(mrow[mt][0] - nm0);
            float sc1 = __expf(mrow[mt][1] - nm1);
            mrow[mt][0] = nm0; mrow[mt][1] = nm1;
            lrow[mt][0] *= sc0; lrow[mt][1] *= sc1;
            #pragma unroll
            for (int nd = 0; nd < 4; nd++) {
                ofr[mt][nd][0] *= sc0; ofr[mt][nd][1] *= sc0;
                ofr[mt][nd][2] *= sc1; ofr[mt][nd][3] *= sc1;
            }
            float ls0 = 0.f, ls1 = 0.f;
            #pragma unroll
            for (int n = 0; n < 4; n++) {
                float p0 = __expf(sfr[mt][n][0] - nm0);
                float p1 = __expf(sfr[mt][n][1] - nm0);
                float p2 = __expf(sfr[mt][n][2] - nm1);
                float p3 = __expf(sfr[mt][n][3] - nm1);
                ls0 += p0 + p1; ls1 += p2 + p3;
                uint32_t h01 = pack_bf16x2(p0, p1);
                uint32_t h23 = pack_bf16x2(p2, p3);
                phr0[mt][n] = h01;
                phr1[mt][n] = h23;
                plr0[mt][n] = pack_bf16x2(p0 - bf_low(h01), p1 - bf_high(h01));
                plr1[mt][n] = pack_bf16x2(p2 - bf_low(h23), p3 - bf_high(h23));
            }
            lrow[mt][0] += ls0; lrow[mt][1] += ls1;
        }

        // ---- O += P V  (bf16 3-term) ----
        #pragma unroll
        for (int nd = 0; nd < 4; nd++) {
            #pragma unroll
            for (int k2 = 0; k2 < 2; k2++) {
                uint32_t bhi[2], blo[2];
                bhi[0] = Vsh[bufc][0][nd*8 + g][k2*8 + j];
                bhi[1] = Vsh[bufc][0][nd*8 + g][k2*8 + j + 4];
                blo[0] = Vsh[bufc][1][nd*8 + g][k2*8 + j];
                blo[1] = Vsh[bufc][1][nd*8 + g][k2*8 + j + 4];
                #pragma unroll
                for (int mt = 0; mt < 2; mt++) {
                    uint32_t ahi[4] = {phr0[mt][2*k2], phr1[mt][2*k2],
                                       phr0[mt][2*k2+1], phr1[mt][2*k2+1]};
                    uint32_t alo[4] = {plr0[mt][2*k2], plr1[mt][2*k2],
                                       plr0[mt][2*k2+1], plr1[mt][2*k2+1]};
                    mma_bf16(ofr[mt][nd], ahi, bhi);
                    mma_bf16(ofr[mt][nd], ahi, blo);
                    mma_bf16(ofr[mt][nd], alo, bhi);
                }
            }
        }

        // ---- stage next tile into other buffer ----
        if (it + 1 < NIT) {
            int bufn = bufc ^ 1;
            float kv[8] = {ka.x,ka.y,ka.z,ka.w,kb2.x,kb2.y,kb2.z,kb2.w};
            #pragma unroll
            for (int i = 0; i < 4; i++) {
                uint32_t hp = pack_bf16x2(kv[2*i], kv[2*i+1]);
                Ksh[bufn][0][(kdb>>1)+i][kkey] = hp;
                Ksh[bufn][1][(kdb>>1)+i][kkey] =
                    pack_bf16x2(kv[2*i] - bf_low(hp), kv[2*i+1] - bf_high(hp));
            }
            float vv[8] = {va.x,va.y,va.z,va.w,vb2.x,vb2.y,vb2.z,vb2.w};
            #pragma unroll
            for (int p = 0; p < 4; p++) {
                uint32_t hp = pack_bf16x2(vv[2*p], vv[2*p+1]);
                Vsh[bufn][0][vdim][vkg*4+p] = hp;
                Vsh[bufn][1][vdim][vkg*4+p] =
                    pack_bf16x2(vv[2*p] - bf_low(hp), vv[2*p+1] - bf_high(hp));
            }
            if (tid < KT) sMask[bufn][tid] = ml;
        }
        __syncthreads();
    }

    // ---- epilogue ----
    #pragma unroll
    for (int mt = 0; mt < 2; mt++) {
        float l0 = lrow[mt][0], l1 = lrow[mt][1];
        l0 += __shfl_xor_sync(0xffffffffu, l0, 1);
        l0 += __shfl_xor_sync(0xffffffffu, l0, 2);
        l1 += __shfl_xor_sync(0xffffffffu, l1, 1);
        l1 += __shfl_xor_sync(0xffffffffu, l1, 2);
        float inv0 = 1.0f / l0, inv1 = 1.0f / l1;
        int r0 = q0 + mt*16 + g;
        #pragma unroll
        for (int nd = 0; nd < 4; nd++) {
            int col = h*DH + nd*8 + 2*j;
            float2 v0 = make_float2(ofr[mt][nd][0]*inv0, ofr[mt][nd][1]*inv0);
            float2 v1 = make_float2(ofr[mt][nd][2]*inv1, ofr[mt][nd][3]*inv1);
            *(float2*)(go + ((size_t)b*SEQ + r0)*DM + col)     = v0;
            *(float2*)(go + ((size_t)b*SEQ + r0 + 8)*DM + col) = v1;
        }
    }
}

// ================= launch =================
extern "C" void kernel_launch(void* const* d_in, const int* in_sizes, int n_in,
                              void* d_out, int out_size) {
    const float* x    = (const float*)d_in[0];
    const float* mask = (const float*)d_in[1];
    const float* Wq   = (const float*)d_in[2];
    const float* Wk   = (const float*)d_in[3];
    const float* Wv   = (const float*)d_in[4];
    const float* Wo   = (const float*)d_in[5];
    const float* W1   = (const float*)d_in[6];
    const float* b1   = (const float*)d_in[7];
    const float* W2   = (const float*)d_in[8];
    const float* b2   = (const float*)d_in[9];
    float* out = (float*)d_out;

    float *wqkv_p, *qkv_p, *vt_p, *o_p, *xc_p, *ff_p;
    cudaGetSymbolAddress((void**)&wqkv_p, g_wqkv);
    cudaGetSymbolAddress((void**)&qkv_p,  g_qkv);
    cudaGetSymbolAddress((void**)&vt_p,   g_vt);
    cudaGetSymbolAddress((void**)&o_p,    g_obuf);
    cudaGetSymbolAddress((void**)&xc_p,   g_xc);
    cudaGetSymbolAddress((void**)&ff_p,   g_ff);

    prep_w_kernel<<<(NL*NH*DM*DH + 255) / 256, 256>>>(Wq, Wk, Wv);

    const size_t QKV_STRIDE = (size_t)MR * DM;

    for (int n = 0; n < NL; n++) {
        const float* xin = (n == 0) ? x : xc_p;

        gemm_fused<<<dim3(DM/BN, MR/BM, 3), 256>>>(
            xin, wqkv_p + (size_t)n * 3 * DM * DM, nullptr, nullptr,
            qkv_p, MR, DM, DM, 0);

        transpose_v<<<dim3(SEQ/32, NB*NH), dim3(32, 8)>>>(
            qkv_p + 2*QKV_STRIDE, vt_p);

        attn_mma<<<dim3(SEQ/128, NB*NH), 128>>>(
            qkv_p, qkv_p + QKV_STRIDE, vt_p, mask, o_p);

        gemm_fused<<<dim3(DM/BN, MR/BM, 1), 256>>>(
            o_p, Wo + (size_t)n * DM * DM, nullptr, xin,
            xc_p, MR, DM, DM, 1);

        gemm_fused<<<dim3(DF/BN, MR/BM, 1), 256>>>(
            xc_p, W1 + (size_t)n * DM * DF, b1 + (size_t)n * DF, nullptr,
            ff_p, MR, DF, DM, 2);

        float* dst = (n == NL - 1) ? out : xc_p;
        gemm_fused<<<dim3(DM/BN, MR/BM, 1), 256>>>(
            ff_p, W2 + (size_t)n * DF * DM, b2 + (size_t)n * DM, xc_p,
            dst, MR, DM, DF, 3);
    }
}

// round 6
// speedup vs baseline: 2.6544x; 1.2656x over previous
#include <cuda_runtime.h>
#include <math.h>
#include <stdint.h>

#define NL   4
#define NB   4
#define SEQ  2048
#define DM   256
#define NH   8
#define DH   32
#define DF   512
#define MR   (NB*SEQ)

#define NEGF (-3.402823466e38f)

typedef unsigned long long u64;

// ================= bf16 helpers =================
// pack two f32 -> bf16x2 (first arg in low 16 bits)
__device__ __forceinline__ uint32_t pack_bf16x2(float lo, float hi) {
    uint32_t r; asm("cvt.rn.bf16x2.f32 %0, %1, %2;" : "=r"(r) : "f"(hi), "f"(lo)); return r;
}
__device__ __forceinline__ float bf_low(uint32_t p)  { return __uint_as_float(p << 16); }
__device__ __forceinline__ float bf_high(uint32_t p) { return __uint_as_float(p & 0xffff0000u); }

__device__ __forceinline__ void mma_bf16(float* c, const uint32_t* a, const uint32_t* b) {
    asm volatile(
        "mma.sync.aligned.m16n8k16.row.col.f32.bf16.bf16.f32 "
        "{%0,%1,%2,%3},{%4,%5,%6,%7},{%8,%9},{%0,%1,%2,%3};"
        : "+f"(c[0]), "+f"(c[1]), "+f"(c[2]), "+f"(c[3])
        : "r"(a[0]), "r"(a[1]), "r"(a[2]), "r"(a[3]), "r"(b[0]), "r"(b[1]));
}

// ================= scratch =================
__device__ float g_qkv [3*(size_t)MR*DM];
__device__ float g_vt  [(size_t)MR*DM];     // V transposed: [b][h][e][l]
__device__ float g_obuf[(size_t)MR*DM];
__device__ float g_xc  [(size_t)MR*DM];
__device__ float g_ff  [(size_t)MR*DF];

// packed bf16 hi/lo weights, layout [n][k-pair] u32 per layer
__device__ uint32_t g_pwqkv_h[NL*3*DM*(DM/2)];
__device__ uint32_t g_pwqkv_l[NL*3*DM*(DM/2)];
__device__ uint32_t g_pwo_h  [NL*DM*(DM/2)];
__device__ uint32_t g_pwo_l  [NL*DM*(DM/2)];
__device__ uint32_t g_pw1_h  [NL*DF*(DM/2)];
__device__ uint32_t g_pw1_l  [NL*DF*(DM/2)];
__device__ uint32_t g_pw2_h  [NL*DM*(DF/2)];
__device__ uint32_t g_pw2_l  [NL*DM*(DF/2)];

// ================= weight packing =================
// QKV: Wq/Wk/Wv [l][h][k=256][e=32] -> [l][m][n=h*32+e][kp=128] hi/lo
__global__ void pack_qkv(const float* __restrict__ Wq,
                         const float* __restrict__ Wk,
                         const float* __restrict__ Wv) {
    int i = blockIdx.x * blockDim.x + threadIdx.x;
    const int PER_M = DM * (DM/2);          // 32768
    const int TOT = NL * 3 * PER_M;
    if (i >= TOT) return;
    int l  = i / (3*PER_M);
    int r  = i % (3*PER_M);
    int m  = r / PER_M;
    int r2 = r % PER_M;
    int n  = r2 >> 7;
    int kp = r2 & 127;
    int h = n >> 5, e = n & 31;
    const float* W = (m == 0) ? Wq : (m == 1) ? Wk : Wv;
    size_t s0 = (((size_t)l*NH + h)*DM + 2*kp)*DH + e;
    float v0 = W[s0], v1 = W[s0 + DH];
    uint32_t hp = pack_bf16x2(v0, v1);
    g_pwqkv_h[i] = hp;
    g_pwqkv_l[i] = pack_bf16x2(v0 - bf_low(hp), v1 - bf_high(hp));
}

// generic: W [l][K][N] -> [l][n][kp] hi/lo
__global__ void pack_w(const float* __restrict__ W, uint32_t* __restrict__ dh,
                       uint32_t* __restrict__ dl, int K, int N) {
    int i = blockIdx.x * blockDim.x + threadIdx.x;
    int per = N * (K >> 1);
    if (i >= NL * per) return;
    int l = i / per, r = i % per;
    int n = r / (K >> 1), kp = r % (K >> 1);
    size_t s = (size_t)l*K*N + (size_t)(2*kp)*N + n;
    float v0 = W[s], v1 = W[s + N];
    uint32_t hp = pack_bf16x2(v0, v1);
    dh[i] = hp;
    dl[i] = pack_bf16x2(v0 - bf_low(hp), v1 - bf_high(hp));
}

// ================= V transpose =================
__global__ void transpose_v(const float* __restrict__ v, float* __restrict__ vt) {
    __shared__ float tl[32][33];
    int bh = blockIdx.y;
    int b = bh >> 3, h = bh & 7;
    int l0 = blockIdx.x * 32;
    #pragma unroll
    for (int k = 0; k < 4; k++) {
        int l = l0 + threadIdx.y + k*8;
        tl[threadIdx.y + k*8][threadIdx.x] = v[((size_t)b*SEQ + l)*DM + h*32 + threadIdx.x];
    }
    __syncthreads();
    #pragma unroll
    for (int k = 0; k < 4; k++) {
        int e = threadIdx.y + k*8;
        vt[((size_t)bh*32 + e)*SEQ + l0 + threadIdx.x] = tl[threadIdx.x][e];
    }
}

// ================= HMMA GEMM (bf16 3-term, double-buffered) =================
// C[M,N] = epi( A[M,K] @ Wt ), Wt pre-packed bf16 hi/lo [n][kpair].
// mode 0: plain (B,C offset by z)   mode 1: (acc+res)*0.5
// mode 2: gelu(acc+bias)            mode 3: (acc+bias+res)*0.5
#define GBM 128
#define GBN 64
#define GBK 32
#define AKP (GBK/2)   // 16 kpairs per tile
#define APAD 20

__device__ __forceinline__ float gelu_exact(float x) {
    return 0.5f * x * (1.0f + erff(x * 0.70710678118654752440f));
}

__device__ __forceinline__ void epi2(float* C, size_t off, float c0, float c1,
                                     float2 bb, const float* res, int mode) {
    float2 o;
    if (mode == 1) {
        float2 r = *(const float2*)(res + off);
        o.x = (c0 + r.x)*0.5f; o.y = (c1 + r.y)*0.5f;
    } else if (mode == 2) {
        o.x = gelu_exact(c0 + bb.x); o.y = gelu_exact(c1 + bb.y);
    } else if (mode == 3) {
        float2 r = *(const float2*)(res + off);
        o.x = (c0 + bb.x + r.x)*0.5f; o.y = (c1 + bb.y + r.y)*0.5f;
    } else {
        o.x = c0; o.y = c1;
    }
    *(float2*)(C + off) = o;
}

extern __shared__ uint32_t dsm[];

__global__ __launch_bounds__(256, 2)
void gemm_mma(const float* __restrict__ A, const uint32_t* __restrict__ Bh,
              const uint32_t* __restrict__ Bl, const float* __restrict__ bias,
              const float* __restrict__ res, float* __restrict__ C,
              int M, int N, int K, int mode) {
    uint32_t* Ash = dsm;                        // [buf][plane][128][APAD]
    uint32_t* Bsh = dsm + 2*2*GBM*APAD;         // [buf][plane][64][APAD]

    if (mode == 0) {
        int z = blockIdx.z;
        Bh += (size_t)z * DM * (DM/2);
        Bl += (size_t)z * DM * (DM/2);
        C  += (size_t)z * (size_t)M * N;
    }
    int bm = blockIdx.y * GBM;
    int bn = blockIdx.x * GBN;
    int tid = threadIdx.x;
    int warp = tid >> 5, lane = tid & 31;
    int g = lane >> 2, j = lane & 3;
    int wm = (warp & 3) * 32;
    int wn = (warp >> 2) * 32;
    int ldkp = K >> 1;

    // producer mapping
    int arow = tid >> 3;              // 0..31 (+32*s)
    int akp0 = (tid & 7) * 2;         // kpair
    int bn0  = tid >> 2;              // 0..63
    int bkp0 = (tid & 3) * 4;

    const float* ap[4];
    #pragma unroll
    for (int s = 0; s < 4; s++)
        ap[s] = A + (size_t)(bm + arow + 32*s)*K + (tid & 7)*4;
    const uint32_t* bph = Bh + (size_t)(bn + bn0)*ldkp + bkp0;
    const uint32_t* bpl = Bl + (size_t)(bn + bn0)*ldkp + bkp0;

    float acc[2][4][4];
    #pragma unroll
    for (int mt = 0; mt < 2; mt++)
        #pragma unroll
        for (int n = 0; n < 4; n++)
            #pragma unroll
            for (int r = 0; r < 4; r++) acc[mt][n][r] = 0.f;

    int nt = K / GBK;
    float4 af[4]; uint4 bfh, bfl;
    #pragma unroll
    for (int s = 0; s < 4; s++) af[s] = *(const float4*)ap[s];
    bfh = *(const uint4*)bph;
    bfl = *(const uint4*)bpl;

    // stage tile 0
    {
        #pragma unroll
        for (int s = 0; s < 4; s++) {
            float4 v = af[s];
            uint32_t h0 = pack_bf16x2(v.x, v.y);
            uint32_t h1 = pack_bf16x2(v.z, v.w);
            uint32_t l0 = pack_bf16x2(v.x - bf_low(h0), v.y - bf_high(h0));
            uint32_t l1 = pack_bf16x2(v.z - bf_low(h1), v.w - bf_high(h1));
            int row = arow + 32*s;
            uint32_t* ph = Ash + row*APAD + akp0;
            uint32_t* pl = Ash + GBM*APAD + row*APAD + akp0;
            ph[0] = h0; ph[1] = h1; pl[0] = l0; pl[1] = l1;
        }
        uint32_t* ph = Bsh + bn0*APAD + bkp0;
        uint32_t* pl = Bsh + GBN*APAD + bn0*APAD + bkp0;
        ph[0]=bfh.x; ph[1]=bfh.y; ph[2]=bfh.z; ph[3]=bfh.w;
        pl[0]=bfl.x; pl[1]=bfl.y; pl[2]=bfl.z; pl[3]=bfl.w;
    }
    __syncthreads();

    for (int t = 0; t < nt; t++) {
        int buf = t & 1;
        if (t + 1 < nt) {
            int k0 = (t+1)*GBK;
            #pragma unroll
            for (int s = 0; s < 4; s++) af[s] = *(const float4*)(ap[s] + k0);
            bfh = *(const uint4*)(bph + (t+1)*AKP);
            bfl = *(const uint4*)(bpl + (t+1)*AKP);
        }

        const uint32_t* Ab = Ash + buf*2*GBM*APAD;
        const uint32_t* Bb = Bsh + buf*2*GBN*APAD;
        #pragma unroll
        for (int kc = 0; kc < 2; kc++) {
            uint32_t ah[2][4], al[2][4];
            #pragma unroll
            for (int mt = 0; mt < 2; mt++) {
                int r0 = wm + mt*16 + g;
                const uint32_t* pa  = Ab;
                const uint32_t* pal = Ab + GBM*APAD;
                ah[mt][0] = pa [(r0)  *APAD + kc*8 + j];
                ah[mt][1] = pa [(r0+8)*APAD + kc*8 + j];
                ah[mt][2] = pa [(r0)  *APAD + kc*8 + j + 4];
                ah[mt][3] = pa [(r0+8)*APAD + kc*8 + j + 4];
                al[mt][0] = pal[(r0)  *APAD + kc*8 + j];
                al[mt][1] = pal[(r0+8)*APAD + kc*8 + j];
                al[mt][2] = pal[(r0)  *APAD + kc*8 + j + 4];
                al[mt][3] = pal[(r0+8)*APAD + kc*8 + j + 4];
            }
            #pragma unroll
            for (int n = 0; n < 4; n++) {
                int c0 = wn + n*8 + g;
                uint32_t bh2[2], bl2[2];
                bh2[0] = Bb[c0*APAD + kc*8 + j];
                bh2[1] = Bb[c0*APAD + kc*8 + j + 4];
                bl2[0] = Bb[GBN*APAD + c0*APAD + kc*8 + j];
                bl2[1] = Bb[GBN*APAD + c0*APAD + kc*8 + j + 4];
                #pragma unroll
                for (int mt = 0; mt < 2; mt++) {
                    mma_bf16(acc[mt][n], ah[mt], bh2);
                    mma_bf16(acc[mt][n], al[mt], bh2);
                    mma_bf16(acc[mt][n], ah[mt], bl2);
                }
            }
        }

        if (t + 1 < nt) {
            int nb = buf ^ 1;
            uint32_t* An = Ash + nb*2*GBM*APAD;
            uint32_t* Bn = Bsh + nb*2*GBN*APAD;
            #pragma unroll
            for (int s = 0; s < 4; s++) {
                float4 v = af[s];
                uint32_t h0 = pack_bf16x2(v.x, v.y);
                uint32_t h1 = pack_bf16x2(v.z, v.w);
                uint32_t l0 = pack_bf16x2(v.x - bf_low(h0), v.y - bf_high(h0));
                uint32_t l1 = pack_bf16x2(v.z - bf_low(h1), v.w - bf_high(h1));
                int row = arow + 32*s;
                uint32_t* ph = An + row*APAD + akp0;
                uint32_t* pl = An + GBM*APAD + row*APAD + akp0;
                ph[0] = h0; ph[1] = h1; pl[0] = l0; pl[1] = l1;
            }
            uint32_t* ph = Bn + bn0*APAD + bkp0;
            uint32_t* pl = Bn + GBN*APAD + bn0*APAD + bkp0;
            ph[0]=bfh.x; ph[1]=bfh.y; ph[2]=bfh.z; ph[3]=bfh.w;
            pl[0]=bfl.x; pl[1]=bfl.y; pl[2]=bfl.z; pl[3]=bfl.w;
        }
        __syncthreads();
    }

    // ---- epilogue ----
    float2 bb[4];
    #pragma unroll
    for (int n = 0; n < 4; n++) {
        if (mode == 2 || mode == 3)
            bb[n] = *(const float2*)(bias + bn + wn + n*8 + 2*j);
        else
            bb[n] = make_float2(0.f, 0.f);
    }
    #pragma unroll
    for (int mt = 0; mt < 2; mt++) {
        int r0 = bm + wm + mt*16 + g;
        #pragma unroll
        for (int n = 0; n < 4; n++) {
            int col = bn + wn + n*8 + 2*j;
            size_t o0 = (size_t)r0*N + col;
            size_t o1 = (size_t)(r0 + 8)*N + col;
            epi2(C, o0, acc[mt][n][0], acc[mt][n][1], bb[n], res, mode);
            epi2(C, o1, acc[mt][n][2], acc[mt][n][3], bb[n], res, mode);
        }
    }
}

// ================= warp-MMA flash attention (all-bf16 3-term, pipelined) ====
#define KT  32
#define NIT (SEQ/KT)

__global__ __launch_bounds__(128, 3)
void attn_mma(const float* __restrict__ gq, const float* __restrict__ gk,
              const float* __restrict__ gvt, const float* __restrict__ gmask,
              float* __restrict__ go) {
    __shared__ uint32_t Ksh[2][2][16][40];
    __shared__ uint32_t Vsh[2][2][32][20];
    __shared__ float    sMask[2][KT];

    int tid  = threadIdx.x;
    int warp = tid >> 5;
    int lane = tid & 31;
    int g    = lane >> 2;
    int j    = lane & 3;
    int bh   = blockIdx.y;
    int b    = bh >> 3, h = bh & 7;
    int q0   = blockIdx.x * 128 + warp * 32;

    uint32_t qh[2][2][4], ql[2][2][4];
    #pragma unroll
    for (int mt = 0; mt < 2; mt++) {
        #pragma unroll
        for (int rr = 0; rr < 2; rr++) {
            int row = q0 + mt*16 + g + rr*8;
            const float* qp = gq + ((size_t)b*SEQ + row)*DM + h*DH;
            #pragma unroll
            for (int u = 0; u < 4; u++) {
                float2 v = *(const float2*)(qp + u*8 + 2*j);
                uint32_t hp = pack_bf16x2(v.x, v.y);
                uint32_t lp = pack_bf16x2(v.x - bf_low(hp), v.y - bf_high(hp));
                qh[mt][u>>1][rr + 2*(u&1)] = hp;
                ql[mt][u>>1][rr + 2*(u&1)] = lp;
            }
        }
    }
    float mqv[2][2];
    #pragma unroll
    for (int mt = 0; mt < 2; mt++) {
        mqv[mt][0] = gmask[b*SEQ + q0 + mt*16 + g];
        mqv[mt][1] = gmask[b*SEQ + q0 + mt*16 + g + 8];
    }

    float mrow[2][2], lrow[2][2], ofr[2][4][4];
    #pragma unroll
    for (int mt = 0; mt < 2; mt++) {
        mrow[mt][0] = NEGF; mrow[mt][1] = NEGF;
        lrow[mt][0] = 0.f;  lrow[mt][1] = 0.f;
        #pragma unroll
        for (int nd = 0; nd < 4; nd++)
            #pragma unroll
            for (int r = 0; r < 4; r++) ofr[mt][nd][r] = 0.f;
    }

    int kkey = lane;
    int kdb  = warp * 8;
    int vdim = tid >> 2;
    int vkg  = tid & 3;
    const float* kbase = gk  + ((size_t)b*SEQ + kkey)*DM + h*DH + kdb;
    const float* vbase = gvt + ((size_t)bh*DH + vdim)*SEQ + vkg*8;
    const float* mbase = gmask + b*SEQ + tid;

    float4 ka, kb2, va, vb2; float ml = 0.f;
    ka  = *(const float4*)(kbase);
    kb2 = *(const float4*)(kbase + 4);
    va  = *(const float4*)(vbase);
    vb2 = *(const float4*)(vbase + 4);
    if (tid < KT) ml = *mbase;

    {
        float kv[8] = {ka.x,ka.y,ka.z,ka.w,kb2.x,kb2.y,kb2.z,kb2.w};
        #pragma unroll
        for (int i = 0; i < 4; i++) {
            uint32_t hp = pack_bf16x2(kv[2*i], kv[2*i+1]);
            Ksh[0][0][(kdb>>1)+i][kkey] = hp;
            Ksh[0][1][(kdb>>1)+i][kkey] =
                pack_bf16x2(kv[2*i] - bf_low(hp), kv[2*i+1] - bf_high(hp));
        }
        float vv[8] = {va.x,va.y,va.z,va.w,vb2.x,vb2.y,vb2.z,vb2.w};
        #pragma unroll
        for (int p = 0; p < 4; p++) {
            uint32_t hp = pack_bf16x2(vv[2*p], vv[2*p+1]);
            Vsh[0][0][vdim][vkg*4+p] = hp;
            Vsh[0][1][vdim][vkg*4+p] =
                pack_bf16x2(vv[2*p] - bf_low(hp), vv[2*p+1] - bf_high(hp));
        }
        if (tid < KT) sMask[0][tid] = ml;
    }
    __syncthreads();

    for (int it = 0; it < NIT; it++) {
        int bufc = it & 1;
        if (it + 1 < NIT) {
            const float* kp = kbase + (size_t)(it+1)*KT*DM;
            const float* vp = vbase + (it+1)*KT;
            ka  = *(const float4*)(kp);
            kb2 = *(const float4*)(kp + 4);
            va  = *(const float4*)(vp);
            vb2 = *(const float4*)(vp + 4);
            if (tid < KT) ml = mbase[(it+1)*KT];
        }

        float sfr[2][4][4];
        #pragma unroll
        for (int mt = 0; mt < 2; mt++)
            #pragma unroll
            for (int n = 0; n < 4; n++)
                #pragma unroll
                for (int r = 0; r < 4; r++) sfr[mt][n][r] = 0.f;

        #pragma unroll
        for (int n = 0; n < 4; n++) {
            #pragma unroll
            for (int ks = 0; ks < 2; ks++) {
                uint32_t bhi[2], blo[2];
                bhi[0] = Ksh[bufc][0][ks*8 + j][n*8 + g];
                bhi[1] = Ksh[bufc][0][ks*8 + j + 4][n*8 + g];
                blo[0] = Ksh[bufc][1][ks*8 + j][n*8 + g];
                blo[1] = Ksh[bufc][1][ks*8 + j + 4][n*8 + g];
                #pragma unroll
                for (int mt = 0; mt < 2; mt++) {
                    mma_bf16(sfr[mt][n], qh[mt][ks], bhi);
                    mma_bf16(sfr[mt][n], ql[mt][ks], bhi);
                    mma_bf16(sfr[mt][n], qh[mt][ks], blo);
                }
            }
        }

        uint32_t phr0[2][4], phr1[2][4], plr0[2][4], plr1[2][4];
        #pragma unroll
        for (int mt = 0; mt < 2; mt++) {
            float mq0 = mqv[mt][0], mq1 = mqv[mt][1];
            float rmax0 = NEGF, rmax1 = NEGF;
            #pragma unroll
            for (int n = 0; n < 4; n++) {
                float mk0 = sMask[bufc][n*8 + 2*j];
                float mk1 = sMask[bufc][n*8 + 2*j + 1];
                float s0 = fmaf(fmaf(-mq0, mk0, 1.0f), NEGF, sfr[mt][n][0]);
                float s1 = fmaf(fmaf(-mq0, mk1, 1.0f), NEGF, sfr[mt][n][1]);
                float s2 = fmaf(fmaf(-mq1, mk0, 1.0f), NEGF, sfr[mt][n][2]);
                float s3 = fmaf(fmaf(-mq1, mk1, 1.0f), NEGF, sfr[mt][n][3]);
                sfr[mt][n][0] = s0; sfr[mt][n][1] = s1;
                sfr[mt][n][2] = s2; sfr[mt][n][3] = s3;
                rmax0 = fmaxf(rmax0, fmaxf(s0, s1));
                rmax1 = fmaxf(rmax1, fmaxf(s2, s3));
            }
            rmax0 = fmaxf(rmax0, __shfl_xor_sync(0xffffffffu, rmax0, 1));
            rmax0 = fmaxf(rmax0, __shfl_xor_sync(0xffffffffu, rmax0, 2));
            rmax1 = fmaxf(rmax1, __shfl_xor_sync(0xffffffffu, rmax1, 1));
            rmax1 = fmaxf(rmax1, __shfl_xor_sync(0xffffffffu, rmax1, 2));

            float nm0 = fmaxf(mrow[mt][0], rmax0);
            float nm1 = fmaxf(mrow[mt][1], rmax1);
            float sc0 = __expf(mrow[mt][0] - nm0);
            float sc1 = __expf(mrow[mt][1] - nm1);
            mrow[mt][0] = nm0; mrow[mt][1] = nm1;
            lrow[mt][0] *= sc0; lrow[mt][1] *= sc1;
            #pragma unroll
            for (int nd = 0; nd < 4; nd++) {
                ofr[mt][nd][0] *= sc0; ofr[mt][nd][1] *= sc0;
                ofr[mt][nd][2] *= sc1; ofr[mt][nd][3] *= sc1;
            }
            float ls0 = 0.f, ls1 = 0.f;
            #pragma unroll
            for (int n = 0; n < 4; n++) {
                float p0 = __expf(sfr[mt][n][0] - nm0);
                float p1 = __expf(sfr[mt][n][1] - nm0);
                float p2 = __expf(sfr[mt][n][2] - nm1);
                float p3 = __expf(sfr[mt][n][3] - nm1);
                ls0 += p0 + p1; ls1 += p2 + p3;
                uint32_t h01 = pack_bf16x2(p0, p1);
                uint32_t h23 = pack_bf16x2(p2, p3);
                phr0[mt][n] = h01;
                phr1[mt][n] = h23;
                plr0[mt][n] = pack_bf16x2(p0 - bf_low(h01), p1 - bf_high(h01));
                plr1[mt][n] = pack_bf16x2(p2 - bf_low(h23), p3 - bf_high(h23));
            }
            lrow[mt][0] += ls0; lrow[mt][1] += ls1;
        }

        #pragma unroll
        for (int nd = 0; nd < 4; nd++) {
            #pragma unroll
            for (int k2 = 0; k2 < 2; k2++) {
                uint32_t bhi[2], blo[2];
                bhi[0] = Vsh[bufc][0][nd*8 + g][k2*8 + j];
                bhi[1] = Vsh[bufc][0][nd*8 + g][k2*8 + j + 4];
                blo[0] = Vsh[bufc][1][nd*8 + g][k2*8 + j];
                blo[1] = Vsh[bufc][1][nd*8 + g][k2*8 + j + 4];
                #pragma unroll
                for (int mt = 0; mt < 2; mt++) {
                    uint32_t ahi[4] = {phr0[mt][2*k2], phr1[mt][2*k2],
                                       phr0[mt][2*k2+1], phr1[mt][2*k2+1]};
                    uint32_t alo[4] = {plr0[mt][2*k2], plr1[mt][2*k2],
                                       plr0[mt][2*k2+1], plr1[mt][2*k2+1]};
                    mma_bf16(ofr[mt][nd], ahi, bhi);
                    mma_bf16(ofr[mt][nd], ahi, blo);
                    mma_bf16(ofr[mt][nd], alo, bhi);
                }
            }
        }

        if (it + 1 < NIT) {
            int bufn = bufc ^ 1;
            float kv[8] = {ka.x,ka.y,ka.z,ka.w,kb2.x,kb2.y,kb2.z,kb2.w};
            #pragma unroll
            for (int i = 0; i < 4; i++) {
                uint32_t hp = pack_bf16x2(kv[2*i], kv[2*i+1]);
                Ksh[bufn][0][(kdb>>1)+i][kkey] = hp;
                Ksh[bufn][1][(kdb>>1)+i][kkey] =
                    pack_bf16x2(kv[2*i] - bf_low(hp), kv[2*i+1] - bf_high(hp));
            }
            float vv[8] = {va.x,va.y,va.z,va.w,vb2.x,vb2.y,vb2.z,vb2.w};
            #pragma unroll
            for (int p = 0; p < 4; p++) {
                uint32_t hp = pack_bf16x2(vv[2*p], vv[2*p+1]);
                Vsh[bufn][0][vdim][vkg*4+p] = hp;
                Vsh[bufn][1][vdim][vkg*4+p] =
                    pack_bf16x2(vv[2*p] - bf_low(hp), vv[2*p+1] - bf_high(hp));
            }
            if (tid < KT) sMask[bufn][tid] = ml;
        }
        __syncthreads();
    }

    #pragma unroll
    for (int mt = 0; mt < 2; mt++) {
        float l0 = lrow[mt][0], l1 = lrow[mt][1];
        l0 += __shfl_xor_sync(0xffffffffu, l0, 1);
        l0 += __shfl_xor_sync(0xffffffffu, l0, 2);
        l1 += __shfl_xor_sync(0xffffffffu, l1, 1);
        l1 += __shfl_xor_sync(0xffffffffu, l1, 2);
        float inv0 = 1.0f / l0, inv1 = 1.0f / l1;
        int r0 = q0 + mt*16 + g;
        #pragma unroll
        for (int nd = 0; nd < 4; nd++) {
            int col = h*DH + nd*8 + 2*j;
            float2 v0 = make_float2(ofr[mt][nd][0]*inv0, ofr[mt][nd][1]*inv0);
            float2 v1 = make_float2(ofr[mt][nd][2]*inv1, ofr[mt][nd][3]*inv1);
            *(float2*)(go + ((size_t)b*SEQ + r0)*DM + col)     = v0;
            *(float2*)(go + ((size_t)b*SEQ + r0 + 8)*DM + col) = v1;
        }
    }
}

// ================= launch =================
extern "C" void kernel_launch(void* const* d_in, const int* in_sizes, int n_in,
                              void* d_out, int out_size) {
    const float* x    = (const float*)d_in[0];
    const float* mask = (const float*)d_in[1];
    const float* Wq   = (const float*)d_in[2];
    const float* Wk   = (const float*)d_in[3];
    const float* Wv   = (const float*)d_in[4];
    const float* Wo   = (const float*)d_in[5];
    const float* W1   = (const float*)d_in[6];
    const float* b1   = (const float*)d_in[7];
    const float* W2   = (const float*)d_in[8];
    const float* b2   = (const float*)d_in[9];
    float* out = (float*)d_out;

    float *qkv_p, *vt_p, *o_p, *xc_p, *ff_p;
    uint32_t *pqkh, *pqkl, *pwoh, *pwol, *pw1h, *pw1l, *pw2h, *pw2l;
    cudaGetSymbolAddress((void**)&qkv_p, g_qkv);
    cudaGetSymbolAddress((void**)&vt_p,  g_vt);
    cudaGetSymbolAddress((void**)&o_p,   g_obuf);
    cudaGetSymbolAddress((void**)&xc_p,  g_xc);
    cudaGetSymbolAddress((void**)&ff_p,  g_ff);
    cudaGetSymbolAddress((void**)&pqkh,  g_pwqkv_h);
    cudaGetSymbolAddress((void**)&pqkl,  g_pwqkv_l);
    cudaGetSymbolAddress((void**)&pwoh,  g_pwo_h);
    cudaGetSymbolAddress((void**)&pwol,  g_pwo_l);
    cudaGetSymbolAddress((void**)&pw1h,  g_pw1_h);
    cudaGetSymbolAddress((void**)&pw1l,  g_pw1_l);
    cudaGetSymbolAddress((void**)&pw2h,  g_pw2_h);
    cudaGetSymbolAddress((void**)&pw2l,  g_pw2_l);

    const int SMEM_GEMM = (2*2*GBM*APAD + 2*2*GBN*APAD) * 4;   // 61440 B
    cudaFuncSetAttribute(gemm_mma, cudaFuncAttributeMaxDynamicSharedMemorySize, SMEM_GEMM);

    // pack weights
    pack_qkv<<<(NL*3*DM*(DM/2) + 255)/256, 256>>>(Wq, Wk, Wv);
    pack_w<<<(NL*DM*(DM/2) + 255)/256, 256>>>(Wo, pwoh, pwol, DM, DM);
    pack_w<<<(NL*DF*(DM/2) + 255)/256, 256>>>(W1, pw1h, pw1l, DM, DF);
    pack_w<<<(NL*DM*(DF/2) + 255)/256, 256>>>(W2, pw2h, pw2l, DF, DM);

    const size_t QKV_STRIDE = (size_t)MR * DM;

    for (int n = 0; n < NL; n++) {
        const float* xin = (n == 0) ? x : xc_p;

        // QKV
        gemm_mma<<<dim3(DM/GBN, MR/GBM, 3), 256, SMEM_GEMM>>>(
            xin, pqkh + (size_t)n*3*DM*(DM/2), pqkl + (size_t)n*3*DM*(DM/2),
            nullptr, nullptr, qkv_p, MR, DM, DM, 0);

        transpose_v<<<dim3(SEQ/32, NB*NH), dim3(32, 8)>>>(
            qkv_p + 2*QKV_STRIDE, vt_p);

        attn_mma<<<dim3(SEQ/128, NB*NH), 128>>>(
            qkv_p, qkv_p + QKV_STRIDE, vt_p, mask, o_p);

        // xc = (o @ Wo + xin) * 0.5
        gemm_mma<<<dim3(DM/GBN, MR/GBM, 1), 256, SMEM_GEMM>>>(
            o_p, pwoh + (size_t)n*DM*(DM/2), pwol + (size_t)n*DM*(DM/2),
            nullptr, xin, xc_p, MR, DM, DM, 1);

        // ff = gelu(xc @ W1 + b1)
        gemm_mma<<<dim3(DF/GBN, MR/GBM, 1), 256, SMEM_GEMM>>>(
            xc_p, pw1h + (size_t)n*DF*(DM/2), pw1l + (size_t)n*DF*(DM/2),
            b1 + (size_t)n*DF, nullptr, ff_p, MR, DF, DM, 2);

        // xc = (ff @ W2 + b2 + xc) * 0.5
        float* dst = (n == NL - 1) ? out : xc_p;
        gemm_mma<<<dim3(DM/GBN, MR/GBM, 1), 256, SMEM_GEMM>>>(
            ff_p, pw2h + (size_t)n*DM*(DF/2), pw2l + (size_t)n*DM*(DF/2),
            b2 + (size_t)n*DM, xc_p, dst, MR, DM, DF, 3);
    }
}

// round 7
// speedup vs baseline: 2.8140x; 1.0601x over previous
#include <cuda_runtime.h>
#include <math.h>
#include <stdint.h>

#define NL   4
#define NB   4
#define SEQ  2048
#define DM   256
#define NH   8
#define DH   32
#define DF   512
#define MR   (NB*SEQ)

#define NEGF (-3.402823466e38f)

typedef unsigned long long u64;

// ================= bf16 helpers =================
// pack two f32 -> bf16x2 (first arg in low 16 bits)
__device__ __forceinline__ uint32_t pack_bf16x2(float lo, float hi) {
    uint32_t r; asm("cvt.rn.bf16x2.f32 %0, %1, %2;" : "=r"(r) : "f"(hi), "f"(lo)); return r;
}
__device__ __forceinline__ float bf_low(uint32_t p)  { return __uint_as_float(p << 16); }
__device__ __forceinline__ float bf_high(uint32_t p) { return __uint_as_float(p & 0xffff0000u); }

__device__ __forceinline__ void mma_bf16(float* c, const uint32_t* a, const uint32_t* b) {
    asm volatile(
        "mma.sync.aligned.m16n8k16.row.col.f32.bf16.bf16.f32 "
        "{%0,%1,%2,%3},{%4,%5,%6,%7},{%8,%9},{%0,%1,%2,%3};"
        : "+f"(c[0]), "+f"(c[1]), "+f"(c[2]), "+f"(c[3])
        : "r"(a[0]), "r"(a[1]), "r"(a[2]), "r"(a[3]), "r"(b[0]), "r"(b[1]));
}

// ================= scratch =================
__device__ float g_qkv [3*(size_t)MR*DM];
__device__ float g_obuf[(size_t)MR*DM];
__device__ float g_xc  [(size_t)MR*DM];
__device__ float g_ff  [(size_t)MR*DF];

// packed K: [bh][dim-pair 16][key 2048] hi/lo;  packed V: [bh][dim 32][key-pair 1024] hi/lo
__device__ uint32_t g_kph[NB*NH*16*SEQ];
__device__ uint32_t g_kpl[NB*NH*16*SEQ];
__device__ uint32_t g_vph[NB*NH*32*(SEQ/2)];
__device__ uint32_t g_vpl[NB*NH*32*(SEQ/2)];

// packed bf16 hi/lo weights, layout [n][k-pair] u32 per layer
__device__ uint32_t g_pwqkv_h[NL*3*DM*(DM/2)];
__device__ uint32_t g_pwqkv_l[NL*3*DM*(DM/2)];
__device__ uint32_t g_pwo_h  [NL*DM*(DM/2)];
__device__ uint32_t g_pwo_l  [NL*DM*(DM/2)];
__device__ uint32_t g_pw1_h  [NL*DF*(DM/2)];
__device__ uint32_t g_pw1_l  [NL*DF*(DM/2)];
__device__ uint32_t g_pw2_h  [NL*DM*(DF/2)];
__device__ uint32_t g_pw2_l  [NL*DM*(DF/2)];

// ================= weight packing =================
__global__ void pack_qkv(const float* __restrict__ Wq,
                         const float* __restrict__ Wk,
                         const float* __restrict__ Wv) {
    int i = blockIdx.x * blockDim.x + threadIdx.x;
    const int PER_M = DM * (DM/2);
    const int TOT = NL * 3 * PER_M;
    if (i >= TOT) return;
    int l  = i / (3*PER_M);
    int r  = i % (3*PER_M);
    int m  = r / PER_M;
    int r2 = r % PER_M;
    int n  = r2 >> 7;
    int kp = r2 & 127;
    int h = n >> 5, e = n & 31;
    const float* W = (m == 0) ? Wq : (m == 1) ? Wk : Wv;
    size_t s0 = (((size_t)l*NH + h)*DM + 2*kp)*DH + e;
    float v0 = W[s0], v1 = W[s0 + DH];
    uint32_t hp = pack_bf16x2(v0, v1);
    g_pwqkv_h[i] = hp;
    g_pwqkv_l[i] = pack_bf16x2(v0 - bf_low(hp), v1 - bf_high(hp));
}

__global__ void pack_w(const float* __restrict__ W, uint32_t* __restrict__ dh,
                       uint32_t* __restrict__ dl, int K, int N) {
    int i = blockIdx.x * blockDim.x + threadIdx.x;
    int per = N * (K >> 1);
    if (i >= NL * per) return;
    int l = i / per, r = i % per;
    int n = r / (K >> 1), kp = r % (K >> 1);
    size_t s = (size_t)l*K*N + (size_t)(2*kp)*N + n;
    float v0 = W[s], v1 = W[s + N];
    uint32_t hp = pack_bf16x2(v0, v1);
    dh[i] = hp;
    dl[i] = pack_bf16x2(v0 - bf_low(hp), v1 - bf_high(hp));
}

// ================= K/V transpose + split-bf16 pack =================
// z=0: K [l][e] -> kp[bh][dp][l] (dims 2dp,2dp+1 packed)
// z=1: V [l][e] -> vp[bh][e][lp] (keys 2lp,2lp+1 packed)
__global__ void pack_kv(const float* __restrict__ k, const float* __restrict__ v) {
    __shared__ float tl[32][33];
    int bh = blockIdx.y;
    int b = bh >> 3, h = bh & 7;
    int l0 = blockIdx.x * 32;
    const float* src = (blockIdx.z == 0) ? k : v;
    #pragma unroll
    for (int kk = 0; kk < 4; kk++) {
        int l = l0 + threadIdx.y + kk*8;
        tl[threadIdx.y + kk*8][threadIdx.x] = src[((size_t)b*SEQ + l)*DM + h*32 + threadIdx.x];
    }
    __syncthreads();
    if (blockIdx.z == 0) {
        #pragma unroll
        for (int kk = 0; kk < 2; kk++) {
            int dp = threadIdx.y + kk*8;
            float v0 = tl[threadIdx.x][2*dp], v1 = tl[threadIdx.x][2*dp+1];
            uint32_t hp = pack_bf16x2(v0, v1);
            size_t o = ((size_t)bh*16 + dp)*SEQ + l0 + threadIdx.x;
            g_kph[o] = hp;
            g_kpl[o] = pack_bf16x2(v0 - bf_low(hp), v1 - bf_high(hp));
        }
    } else {
        #pragma unroll
        for (int kk = 0; kk < 2; kk++) {
            int idx = threadIdx.y*32 + threadIdx.x + kk*256;  // 0..511
            int e = idx >> 4, lp = idx & 15;
            float v0 = tl[2*lp][e], v1 = tl[2*lp+1][e];
            uint32_t hp = pack_bf16x2(v0, v1);
            size_t o = ((size_t)bh*32 + e)*(SEQ/2) + (l0 >> 1) + lp;
            g_vph[o] = hp;
            g_vpl[o] = pack_bf16x2(v0 - bf_low(hp), v1 - bf_high(hp));
        }
    }
}

// ================= HMMA GEMM (bf16 3-term, double-buffered) =================
#define GBM 128
#define GBN 64
#define GBK 32
#define AKP (GBK/2)
#define APAD 20

__device__ __forceinline__ float gelu_exact(float x) {
    return 0.5f * x * (1.0f + erff(x * 0.70710678118654752440f));
}

__device__ __forceinline__ void epi2(float* C, size_t off, float c0, float c1,
                                     float2 bb, const float* res, int mode) {
    float2 o;
    if (mode == 1) {
        float2 r = *(const float2*)(res + off);
        o.x = (c0 + r.x)*0.5f; o.y = (c1 + r.y)*0.5f;
    } else if (mode == 2) {
        o.x = gelu_exact(c0 + bb.x); o.y = gelu_exact(c1 + bb.y);
    } else if (mode == 3) {
        float2 r = *(const float2*)(res + off);
        o.x = (c0 + bb.x + r.x)*0.5f; o.y = (c1 + bb.y + r.y)*0.5f;
    } else {
        o.x = c0; o.y = c1;
    }
    *(float2*)(C + off) = o;
}

extern __shared__ uint32_t dsm[];

__global__ __launch_bounds__(256, 2)
void gemm_mma(const float* __restrict__ A, const uint32_t* __restrict__ Bh,
              const uint32_t* __restrict__ Bl, const float* __restrict__ bias,
              const float* __restrict__ res, float* __restrict__ C,
              int M, int N, int K, int mode) {
    uint32_t* Ash = dsm;
    uint32_t* Bsh = dsm + 2*2*GBM*APAD;

    if (mode == 0) {
        int z = blockIdx.z;
        Bh += (size_t)z * DM * (DM/2);
        Bl += (size_t)z * DM * (DM/2);
        C  += (size_t)z * (size_t)M * N;
    }
    int bm = blockIdx.y * GBM;
    int bn = blockIdx.x * GBN;
    int tid = threadIdx.x;
    int warp = tid >> 5, lane = tid & 31;
    int g = lane >> 2, j = lane & 3;
    int wm = (warp & 3) * 32;
    int wn = (warp >> 2) * 32;
    int ldkp = K >> 1;

    int arow = tid >> 3;
    int akp0 = (tid & 7) * 2;
    int bn0  = tid >> 2;
    int bkp0 = (tid & 3) * 4;

    const float* ap[4];
    #pragma unroll
    for (int s = 0; s < 4; s++)
        ap[s] = A + (size_t)(bm + arow + 32*s)*K + (tid & 7)*4;
    const uint32_t* bph = Bh + (size_t)(bn + bn0)*ldkp + bkp0;
    const uint32_t* bpl = Bl + (size_t)(bn + bn0)*ldkp + bkp0;

    float acc[2][4][4];
    #pragma unroll
    for (int mt = 0; mt < 2; mt++)
        #pragma unroll
        for (int n = 0; n < 4; n++)
            #pragma unroll
            for (int r = 0; r < 4; r++) acc[mt][n][r] = 0.f;

    int nt = K / GBK;
    float4 af[4]; uint4 bfh, bfl;
    #pragma unroll
    for (int s = 0; s < 4; s++) af[s] = *(const float4*)ap[s];
    bfh = *(const uint4*)bph;
    bfl = *(const uint4*)bpl;

    {
        #pragma unroll
        for (int s = 0; s < 4; s++) {
            float4 v = af[s];
            uint32_t h0 = pack_bf16x2(v.x, v.y);
            uint32_t h1 = pack_bf16x2(v.z, v.w);
            uint32_t l0 = pack_bf16x2(v.x - bf_low(h0), v.y - bf_high(h0));
            uint32_t l1 = pack_bf16x2(v.z - bf_low(h1), v.w - bf_high(h1));
            int row = arow + 32*s;
            uint32_t* ph = Ash + row*APAD + akp0;
            uint32_t* pl = Ash + GBM*APAD + row*APAD + akp0;
            ph[0] = h0; ph[1] = h1; pl[0] = l0; pl[1] = l1;
        }
        uint32_t* ph = Bsh + bn0*APAD + bkp0;
        uint32_t* pl = Bsh + GBN*APAD + bn0*APAD + bkp0;
        ph[0]=bfh.x; ph[1]=bfh.y; ph[2]=bfh.z; ph[3]=bfh.w;
        pl[0]=bfl.x; pl[1]=bfl.y; pl[2]=bfl.z; pl[3]=bfl.w;
    }
    __syncthreads();

    for (int t = 0; t < nt; t++) {
        int buf = t & 1;
        if (t + 1 < nt) {
            int k0 = (t+1)*GBK;
            #pragma unroll
            for (int s = 0; s < 4; s++) af[s] = *(const float4*)(ap[s] + k0);
            bfh = *(const uint4*)(bph + (t+1)*AKP);
            bfl = *(const uint4*)(bpl + (t+1)*AKP);
        }

        const uint32_t* Ab = Ash + buf*2*GBM*APAD;
        const uint32_t* Bb = Bsh + buf*2*GBN*APAD;
        #pragma unroll
        for (int kc = 0; kc < 2; kc++) {
            uint32_t ah[2][4], al[2][4];
            #pragma unroll
            for (int mt = 0; mt < 2; mt++) {
                int r0 = wm + mt*16 + g;
                const uint32_t* pa  = Ab;
                const uint32_t* pal = Ab + GBM*APAD;
                ah[mt][0] = pa [(r0)  *APAD + kc*8 + j];
                ah[mt][1] = pa [(r0+8)*APAD + kc*8 + j];
                ah[mt][2] = pa [(r0)  *APAD + kc*8 + j + 4];
                ah[mt][3] = pa [(r0+8)*APAD + kc*8 + j + 4];
                al[mt][0] = pal[(r0)  *APAD + kc*8 + j];
                al[mt][1] = pal[(r0+8)*APAD + kc*8 + j];
                al[mt][2] = pal[(r0)  *APAD + kc*8 + j + 4];
                al[mt][3] = pal[(r0+8)*APAD + kc*8 + j + 4];
            }
            #pragma unroll
            for (int n = 0; n < 4; n++) {
                int c0 = wn + n*8 + g;
                uint32_t bh2[2], bl2[2];
                bh2[0] = Bb[c0*APAD + kc*8 + j];
                bh2[1] = Bb[c0*APAD + kc*8 + j + 4];
                bl2[0] = Bb[GBN*APAD + c0*APAD + kc*8 + j];
                bl2[1] = Bb[GBN*APAD + c0*APAD + kc*8 + j + 4];
                #pragma unroll
                for (int mt = 0; mt < 2; mt++) {
                    mma_bf16(acc[mt][n], ah[mt], bh2);
                    mma_bf16(acc[mt][n], al[mt], bh2);
                    mma_bf16(acc[mt][n], ah[mt], bl2);
                }
            }
        }

        if (t + 1 < nt) {
            int nb = buf ^ 1;
            uint32_t* An = Ash + nb*2*GBM*APAD;
            uint32_t* Bn = Bsh + nb*2*GBN*APAD;
            #pragma unroll
            for (int s = 0; s < 4; s++) {
                float4 v = af[s];
                uint32_t h0 = pack_bf16x2(v.x, v.y);
                uint32_t h1 = pack_bf16x2(v.z, v.w);
                uint32_t l0 = pack_bf16x2(v.x - bf_low(h0), v.y - bf_high(h0));
                uint32_t l1 = pack_bf16x2(v.z - bf_low(h1), v.w - bf_high(h1));
                int row = arow + 32*s;
                uint32_t* ph = An + row*APAD + akp0;
                uint32_t* pl = An + GBM*APAD + row*APAD + akp0;
                ph[0] = h0; ph[1] = h1; pl[0] = l0; pl[1] = l1;
            }
            uint32_t* ph = Bn + bn0*APAD + bkp0;
            uint32_t* pl = Bn + GBN*APAD + bn0*APAD + bkp0;
            ph[0]=bfh.x; ph[1]=bfh.y; ph[2]=bfh.z; ph[3]=bfh.w;
            pl[0]=bfl.x; pl[1]=bfl.y; pl[2]=bfl.z; pl[3]=bfl.w;
        }
        __syncthreads();
    }

    float2 bb[4];
    #pragma unroll
    for (int n = 0; n < 4; n++) {
        if (mode == 2 || mode == 3)
            bb[n] = *(const float2*)(bias + bn + wn + n*8 + 2*j);
        else
            bb[n] = make_float2(0.f, 0.f);
    }
    #pragma unroll
    for (int mt = 0; mt < 2; mt++) {
        int r0 = bm + wm + mt*16 + g;
        #pragma unroll
        for (int n = 0; n < 4; n++) {
            int col = bn + wn + n*8 + 2*j;
            size_t o0 = (size_t)r0*N + col;
            size_t o1 = (size_t)(r0 + 8)*N + col;
            epi2(C, o0, acc[mt][n][0], acc[mt][n][1], bb[n], res, mode);
            epi2(C, o1, acc[mt][n][2], acc[mt][n][3], bb[n], res, mode);
        }
    }
}

// ================= warp-MMA flash attention (prepacked K/V) =================
#define KT  32
#define NIT (SEQ/KT)

__global__ __launch_bounds__(128, 3)
void attn_mma(const float* __restrict__ gq, const float* __restrict__ gmask,
              float* __restrict__ go) {
    __shared__ __align__(16) uint32_t Ksh[2][2][16][40];
    __shared__ __align__(16) uint32_t Vsh[2][2][32][20];
    __shared__ float sMask[2][KT];

    int tid  = threadIdx.x;
    int warp = tid >> 5;
    int lane = tid & 31;
    int g    = lane >> 2;
    int j    = lane & 3;
    int bh   = blockIdx.y;
    int b    = bh >> 3, h = bh & 7;
    int q0   = blockIdx.x * 128 + warp * 32;

    uint32_t qh[2][2][4], ql[2][2][4];
    #pragma unroll
    for (int mt = 0; mt < 2; mt++) {
        #pragma unroll
        for (int rr = 0; rr < 2; rr++) {
            int row = q0 + mt*16 + g + rr*8;
            const float* qp = gq + ((size_t)b*SEQ + row)*DM + h*DH;
            #pragma unroll
            for (int u = 0; u < 4; u++) {
                float2 v = *(const float2*)(qp + u*8 + 2*j);
                uint32_t hp = pack_bf16x2(v.x, v.y);
                uint32_t lp = pack_bf16x2(v.x - bf_low(hp), v.y - bf_high(hp));
                qh[mt][u>>1][rr + 2*(u&1)] = hp;
                ql[mt][u>>1][rr + 2*(u&1)] = lp;
            }
        }
    }
    float mqv[2][2];
    #pragma unroll
    for (int mt = 0; mt < 2; mt++) {
        mqv[mt][0] = gmask[b*SEQ + q0 + mt*16 + g];
        mqv[mt][1] = gmask[b*SEQ + q0 + mt*16 + g + 8];
    }

    float mrow[2][2], lrow[2][2], ofr[2][4][4];
    #pragma unroll
    for (int mt = 0; mt < 2; mt++) {
        mrow[mt][0] = NEGF; mrow[mt][1] = NEGF;
        lrow[mt][0] = 0.f;  lrow[mt][1] = 0.f;
        #pragma unroll
        for (int nd = 0; nd < 4; nd++)
            #pragma unroll
            for (int r = 0; r < 4; r++) ofr[mt][nd][r] = 0.f;
    }

    // producer bases (prepacked planes)
    int kdp = tid >> 3;              // 0..15
    int kkg = (tid & 7) * 4;         // key offset 0..28
    int vdm = tid >> 2;              // 0..31
    int vpg = (tid & 3) * 4;         // pair offset 0..12
    const uint32_t* kbh = g_kph + ((size_t)bh*16 + kdp)*SEQ + kkg;
    const uint32_t* kbl = g_kpl + ((size_t)bh*16 + kdp)*SEQ + kkg;
    const uint32_t* vbh = g_vph + ((size_t)bh*32 + vdm)*(SEQ/2) + vpg;
    const uint32_t* vbl = g_vpl + ((size_t)bh*32 + vdm)*(SEQ/2) + vpg;
    const float* mbase = gmask + b*SEQ + tid;

    uint4 rkh, rkl, rvh, rvl; float ml = 0.f;
    rkh = *(const uint4*)(kbh);
    rkl = *(const uint4*)(kbl);
    rvh = *(const uint4*)(vbh);
    rvl = *(const uint4*)(vbl);
    if (tid < KT) ml = *mbase;

    *(uint4*)&Ksh[0][0][kdp][kkg] = rkh;
    *(uint4*)&Ksh[0][1][kdp][kkg] = rkl;
    *(uint4*)&Vsh[0][0][vdm][vpg] = rvh;
    *(uint4*)&Vsh[0][1][vdm][vpg] = rvl;
    if (tid < KT) sMask[0][tid] = ml;
    __syncthreads();

    for (int it = 0; it < NIT; it++) {
        int bufc = it & 1;
        if (it + 1 < NIT) {
            rkh = *(const uint4*)(kbh + (it+1)*KT);
            rkl = *(const uint4*)(kbl + (it+1)*KT);
            rvh = *(const uint4*)(vbh + (it+1)*(KT/2));
            rvl = *(const uint4*)(vbl + (it+1)*(KT/2));
            if (tid < KT) ml = mbase[(it+1)*KT];
        }

        float sfr[2][4][4];
        #pragma unroll
        for (int mt = 0; mt < 2; mt++)
            #pragma unroll
            for (int n = 0; n < 4; n++)
                #pragma unroll
                for (int r = 0; r < 4; r++) sfr[mt][n][r] = 0.f;

        #pragma unroll
        for (int n = 0; n < 4; n++) {
            #pragma unroll
            for (int ks = 0; ks < 2; ks++) {
                uint32_t bhi[2], blo[2];
                bhi[0] = Ksh[bufc][0][ks*8 + j][n*8 + g];
                bhi[1] = Ksh[bufc][0][ks*8 + j + 4][n*8 + g];
                blo[0] = Ksh[bufc][1][ks*8 + j][n*8 + g];
                blo[1] = Ksh[bufc][1][ks*8 + j + 4][n*8 + g];
                #pragma unroll
                for (int mt = 0; mt < 2; mt++) {
                    mma_bf16(sfr[mt][n], qh[mt][ks], bhi);
                    mma_bf16(sfr[mt][n], ql[mt][ks], bhi);
                    mma_bf16(sfr[mt][n], qh[mt][ks], blo);
                }
            }
        }

        uint32_t phr0[2][4], phr1[2][4], plr0[2][4], plr1[2][4];
        #pragma unroll
        for (int mt = 0; mt < 2; mt++) {
            float mq0 = mqv[mt][0], mq1 = mqv[mt][1];
            float rmax0 = NEGF, rmax1 = NEGF;
            #pragma unroll
            for (int n = 0; n < 4; n++) {
                float mk0 = sMask[bufc][n*8 + 2*j];
                float mk1 = sMask[bufc][n*8 + 2*j + 1];
                float s0 = fmaf(fmaf(-mq0, mk0, 1.0f), NEGF, sfr[mt][n][0]);
                float s1 = fmaf(fmaf(-mq0, mk1, 1.0f), NEGF, sfr[mt][n][1]);
                float s2 = fmaf(fmaf(-mq1, mk0, 1.0f), NEGF, sfr[mt][n][2]);
                float s3 = fmaf(fmaf(-mq1, mk1, 1.0f), NEGF, sfr[mt][n][3]);
                sfr[mt][n][0] = s0; sfr[mt][n][1] = s1;
                sfr[mt][n][2] = s2; sfr[mt][n][3] = s3;
                rmax0 = fmaxf(rmax0, fmaxf(s0, s1));
                rmax1 = fmaxf(rmax1, fmaxf(s2, s3));
            }
            rmax0 = fmaxf(rmax0, __shfl_xor_sync(0xffffffffu, rmax0, 1));
            rmax0 = fmaxf(rmax0, __shfl_xor_sync(0xffffffffu, rmax0, 2));
            rmax1 = fmaxf(rmax1, __shfl_xor_sync(0xffffffffu, rmax1, 1));
            rmax1 = fmaxf(rmax1, __shfl_xor_sync(0xffffffffu, rmax1, 2));

            float nm0 = fmaxf(mrow[mt][0], rmax0);
            float nm1 = fmaxf(mrow[mt][1], rmax1);
            float sc0 = __expf(mrow[mt][0] - nm0);
            float sc1 = __expf(mrow[mt][1] - nm1);
            mrow[mt][0] = nm0; mrow[mt][1] = nm1;
            lrow[mt][0] *= sc0; lrow[mt][1] *= sc1;
            #pragma unroll
            for (int nd = 0; nd < 4; nd++) {
                ofr[mt][nd][0] *= sc0; ofr[mt][nd][1] *= sc0;
                ofr[mt][nd][2] *= sc1; ofr[mt][nd][3] *= sc1;
            }
            float ls0 = 0.f, ls1 = 0.f;
            #pragma unroll
            for (int n = 0; n < 4; n++) {
                float p0 = __expf(sfr[mt][n][0] - nm0);
                float p1 = __expf(sfr[mt][n][1] - nm0);
                float p2 = __expf(sfr[mt][n][2] - nm1);
                float p3 = __expf(sfr[mt][n][3] - nm1);
                ls0 += p0 + p1; ls1 += p2 + p3;
                uint32_t h01 = pack_bf16x2(p0, p1);
                uint32_t h23 = pack_bf16x2(p2, p3);
                phr0[mt][n] = h01;
                phr1[mt][n] = h23;
                plr0[mt][n] = pack_bf16x2(p0 - bf_low(h01), p1 - bf_high(h01));
                plr1[mt][n] = pack_bf16x2(p2 - bf_low(h23), p3 - bf_high(h23));
            }
            lrow[mt][0] += ls0; lrow[mt][1] += ls1;
        }

        #pragma unroll
        for (int nd = 0; nd < 4; nd++) {
            #pragma unroll
            for (int k2 = 0; k2 < 2; k2++) {
                uint32_t bhi[2], blo[2];
                bhi[0] = Vsh[bufc][0][nd*8 + g][k2*8 + j];
                bhi[1] = Vsh[bufc][0][nd*8 + g][k2*8 + j + 4];
                blo[0] = Vsh[bufc][1][nd*8 + g][k2*8 + j];
                blo[1] = Vsh[bufc][1][nd*8 + g][k2*8 + j + 4];
                #pragma unroll
                for (int mt = 0; mt < 2; mt++) {
                    uint32_t ahi[4] = {phr0[mt][2*k2], phr1[mt][2*k2],
                                       phr0[mt][2*k2+1], phr1[mt][2*k2+1]};
                    uint32_t alo[4] = {plr0[mt][2*k2], plr1[mt][2*k2],
                                       plr0[mt][2*k2+1], plr1[mt][2*k2+1]};
                    mma_bf16(ofr[mt][nd], ahi, bhi);
                    mma_bf16(ofr[mt][nd], ahi, blo);
                    mma_bf16(ofr[mt][nd], alo, bhi);
                }
            }
        }

        if (it + 1 < NIT) {
            int bufn = bufc ^ 1;
            *(uint4*)&Ksh[bufn][0][kdp][kkg] = rkh;
            *(uint4*)&Ksh[bufn][1][kdp][kkg] = rkl;
            *(uint4*)&Vsh[bufn][0][vdm][vpg] = rvh;
            *(uint4*)&Vsh[bufn][1][vdm][vpg] = rvl;
            if (tid < KT) sMask[bufn][tid] = ml;
        }
        __syncthreads();
    }

    #pragma unroll
    for (int mt = 0; mt < 2; mt++) {
        float l0 = lrow[mt][0], l1 = lrow[mt][1];
        l0 += __shfl_xor_sync(0xffffffffu, l0, 1);
        l0 += __shfl_xor_sync(0xffffffffu, l0, 2);
        l1 += __shfl_xor_sync(0xffffffffu, l1, 1);
        l1 += __shfl_xor_sync(0xffffffffu, l1, 2);
        float inv0 = 1.0f / l0, inv1 = 1.0f / l1;
        int r0 = q0 + mt*16 + g;
        #pragma unroll
        for (int nd = 0; nd < 4; nd++) {
            int col = h*DH + nd*8 + 2*j;
            float2 v0 = make_float2(ofr[mt][nd][0]*inv0, ofr[mt][nd][1]*inv0);
            float2 v1 = make_float2(ofr[mt][nd][2]*inv1, ofr[mt][nd][3]*inv1);
            *(float2*)(go + ((size_t)b*SEQ + r0)*DM + col)     = v0;
            *(float2*)(go + ((size_t)b*SEQ + r0 + 8)*DM + col) = v1;
        }
    }
}

// ================= launch =================
extern "C" void kernel_launch(void* const* d_in, const int* in_sizes, int n_in,
                              void* d_out, int out_size) {
    const float* x    = (const float*)d_in[0];
    const float* mask = (const float*)d_in[1];
    const float* Wq   = (const float*)d_in[2];
    const float* Wk   = (const float*)d_in[3];
    const float* Wv   = (const float*)d_in[4];
    const float* Wo   = (const float*)d_in[5];
    const float* W1   = (const float*)d_in[6];
    const float* b1   = (const float*)d_in[7];
    const float* W2   = (const float*)d_in[8];
    const float* b2   = (const float*)d_in[9];
    float* out = (float*)d_out;

    float *qkv_p, *o_p, *xc_p, *ff_p;
    uint32_t *pqkh, *pqkl, *pwoh, *pwol, *pw1h, *pw1l, *pw2h, *pw2l;
    cudaGetSymbolAddress((void**)&qkv_p, g_qkv);
    cudaGetSymbolAddress((void**)&o_p,   g_obuf);
    cudaGetSymbolAddress((void**)&xc_p,  g_xc);
    cudaGetSymbolAddress((void**)&ff_p,  g_ff);
    cudaGetSymbolAddress((void**)&pqkh,  g_pwqkv_h);
    cudaGetSymbolAddress((void**)&pqkl,  g_pwqkv_l);
    cudaGetSymbolAddress((void**)&pwoh,  g_pwo_h);
    cudaGetSymbolAddress((void**)&pwol,  g_pwo_l);
    cudaGetSymbolAddress((void**)&pw1h,  g_pw1_h);
    cudaGetSymbolAddress((void**)&pw1l,  g_pw1_l);
    cudaGetSymbolAddress((void**)&pw2h,  g_pw2_h);
    cudaGetSymbolAddress((void**)&pw2l,  g_pw2_l);

    const int SMEM_GEMM = (2*2*GBM*APAD + 2*2*GBN*APAD) * 4;
    cudaFuncSetAttribute(gemm_mma, cudaFuncAttributeMaxDynamicSharedMemorySize, SMEM_GEMM);

    pack_qkv<<<(NL*3*DM*(DM/2) + 255)/256, 256>>>(Wq, Wk, Wv);
    pack_w<<<(NL*DM*(DM/2) + 255)/256, 256>>>(Wo, pwoh, pwol, DM, DM);
    pack_w<<<(NL*DF*(DM/2) + 255)/256, 256>>>(W1, pw1h, pw1l, DM, DF);
    pack_w<<<(NL*DM*(DF/2) + 255)/256, 256>>>(W2, pw2h, pw2l, DF, DM);

    const size_t QKV_STRIDE = (size_t)MR * DM;

    for (int n = 0; n < NL; n++) {
        const float* xin = (n == 0) ? x : xc_p;

        gemm_mma<<<dim3(DM/GBN, MR/GBM, 3), 256, SMEM_GEMM>>>(
            xin, pqkh + (size_t)n*3*DM*(DM/2), pqkl + (size_t)n*3*DM*(DM/2),
            nullptr, nullptr, qkv_p, MR, DM, DM, 0);

        pack_kv<<<dim3(SEQ/32, NB*NH, 2), dim3(32, 8)>>>(
            qkv_p + QKV_STRIDE, qkv_p + 2*QKV_STRIDE);

        attn_mma<<<dim3(SEQ/128, NB*NH), 128>>>(qkv_p, mask, o_p);

        gemm_mma<<<dim3(DM/GBN, MR/GBM, 1), 256, SMEM_GEMM>>>(
            o_p, pwoh + (size_t)n*DM*(DM/2), pwol + (size_t)n*DM*(DM/2),
            nullptr, xin, xc_p, MR, DM, DM, 1);

        gemm_mma<<<dim3(DF/GBN, MR/GBM, 1), 256, SMEM_GEMM>>>(
            xc_p, pw1h + (size_t)n*DF*(DM/2), pw1l + (size_t)n*DF*(DM/2),
            b1 + (size_t)n*DF, nullptr, ff_p, MR, DF, DM, 2);

        float* dst = (n == NL - 1) ? out : xc_p;
        gemm_mma<<<dim3(DM/GBN, MR/GBM, 1), 256, SMEM_GEMM>>>(
            ff_p, pw2h + (size_t)n*DM*(DF/2), pw2l + (size_t)n*DM*(DF/2),
            b2 + (size_t)n*DM, xc_p, dst, MR, DM, DF, 3);
    }
}

// round 8
// speedup vs baseline: 3.0703x; 1.0911x over previous
#include <cuda_runtime.h>
#include <math.h>
#include <stdint.h>

#define NL   4
#define NB   4
#define SEQ  2048
#define DM   256
#define NH   8
#define DH   32
#define DF   512
#define MR   (NB*SEQ)

#define NEGF (-3.402823466e38f)

typedef unsigned long long u64;

// ================= bf16 helpers =================
__device__ __forceinline__ uint32_t pack_bf16x2(float lo, float hi) {
    uint32_t r; asm("cvt.rn.bf16x2.f32 %0, %1, %2;" : "=r"(r) : "f"(hi), "f"(lo)); return r;
}
__device__ __forceinline__ float bf_low(uint32_t p)  { return __uint_as_float(p << 16); }
__device__ __forceinline__ float bf_high(uint32_t p) { return __uint_as_float(p & 0xffff0000u); }

__device__ __forceinline__ void mma_bf16(float* c, const uint32_t* a, const uint32_t* b) {
    asm volatile(
        "mma.sync.aligned.m16n8k16.row.col.f32.bf16.bf16.f32 "
        "{%0,%1,%2,%3},{%4,%5,%6,%7},{%8,%9},{%0,%1,%2,%3};"
        : "+f"(c[0]), "+f"(c[1]), "+f"(c[2]), "+f"(c[3])
        : "r"(a[0]), "r"(a[1]), "r"(a[2]), "r"(a[3]), "r"(b[0]), "r"(b[1]));
}

// ================= scratch =================
__device__ float g_qkv [3*(size_t)MR*DM];
__device__ float g_obuf[(size_t)MR*DM];
__device__ float g_xc  [(size_t)MR*DM];
__device__ float g_ff  [(size_t)MR*DF];

// packed K: [bh][dim-pair 16][key 2048] hi/lo;  packed V: [bh][dim 32][key-pair 1024] hi/lo
__device__ uint32_t g_kph[NB*NH*16*SEQ];
__device__ uint32_t g_kpl[NB*NH*16*SEQ];
__device__ uint32_t g_vph[NB*NH*32*(SEQ/2)];
__device__ uint32_t g_vpl[NB*NH*32*(SEQ/2)];
__device__ unsigned g_kmax2[NB*NH];        // max ||k||^2 per (b,h), float bits

// packed bf16 hi/lo weights
__device__ uint32_t g_pwqkv_h[NL*3*DM*(DM/2)];
__device__ uint32_t g_pwqkv_l[NL*3*DM*(DM/2)];
__device__ uint32_t g_pwo_h  [NL*DM*(DM/2)];
__device__ uint32_t g_pwo_l  [NL*DM*(DM/2)];
__device__ uint32_t g_pw1_h  [NL*DF*(DM/2)];
__device__ uint32_t g_pw1_l  [NL*DF*(DM/2)];
__device__ uint32_t g_pw2_h  [NL*DM*(DF/2)];
__device__ uint32_t g_pw2_l  [NL*DM*(DF/2)];

// ================= weight packing =================
__global__ void pack_qkv(const float* __restrict__ Wq,
                         const float* __restrict__ Wk,
                         const float* __restrict__ Wv) {
    int i = blockIdx.x * blockDim.x + threadIdx.x;
    const int PER_M = DM * (DM/2);
    const int TOT = NL * 3 * PER_M;
    if (i >= TOT) return;
    int l  = i / (3*PER_M);
    int r  = i % (3*PER_M);
    int m  = r / PER_M;
    int r2 = r % PER_M;
    int n  = r2 >> 7;
    int kp = r2 & 127;
    int h = n >> 5, e = n & 31;
    const float* W = (m == 0) ? Wq : (m == 1) ? Wk : Wv;
    size_t s0 = (((size_t)l*NH + h)*DM + 2*kp)*DH + e;
    float v0 = W[s0], v1 = W[s0 + DH];
    uint32_t hp = pack_bf16x2(v0, v1);
    g_pwqkv_h[i] = hp;
    g_pwqkv_l[i] = pack_bf16x2(v0 - bf_low(hp), v1 - bf_high(hp));
}

__global__ void pack_w(const float* __restrict__ W, uint32_t* __restrict__ dh,
                       uint32_t* __restrict__ dl, int K, int N) {
    int i = blockIdx.x * blockDim.x + threadIdx.x;
    int per = N * (K >> 1);
    if (i >= NL * per) return;
    int l = i / per, r = i % per;
    int n = r / (K >> 1), kp = r % (K >> 1);
    size_t s = (size_t)l*K*N + (size_t)(2*kp)*N + n;
    float v0 = W[s], v1 = W[s + N];
    uint32_t hp = pack_bf16x2(v0, v1);
    dh[i] = hp;
    dl[i] = pack_bf16x2(v0 - bf_low(hp), v1 - bf_high(hp));
}

__global__ void reset_kmax() {
    if (threadIdx.x < NB*NH) g_kmax2[threadIdx.x] = 0u;
}

// ================= K/V transpose + split-bf16 pack (+ K norm max) ==========
__global__ void pack_kv(const float* __restrict__ k, const float* __restrict__ v) {
    __shared__ float tl[32][33];
    int bh = blockIdx.y;
    int b = bh >> 3, h = bh & 7;
    int l0 = blockIdx.x * 32;
    const float* src = (blockIdx.z == 0) ? k : v;
    #pragma unroll
    for (int kk = 0; kk < 4; kk++) {
        int l = l0 + threadIdx.y + kk*8;
        tl[threadIdx.y + kk*8][threadIdx.x] = src[((size_t)b*SEQ + l)*DM + h*32 + threadIdx.x];
    }
    __syncthreads();
    if (blockIdx.z == 0) {
        #pragma unroll
        for (int kk = 0; kk < 2; kk++) {
            int dp = threadIdx.y + kk*8;
            float v0 = tl[threadIdx.x][2*dp], v1 = tl[threadIdx.x][2*dp+1];
            uint32_t hp = pack_bf16x2(v0, v1);
            size_t o = ((size_t)bh*16 + dp)*SEQ + l0 + threadIdx.x;
            g_kph[o] = hp;
            g_kpl[o] = pack_bf16x2(v0 - bf_low(hp), v1 - bf_high(hp));
        }
        // K row norms (warp 0 = threads y==0): lane x handles key l0+x
        if (threadIdx.y == 0) {
            float n2 = 0.f;
            #pragma unroll
            for (int e = 0; e < 32; e++) n2 = fmaf(tl[threadIdx.x][e], tl[threadIdx.x][e], n2);
            #pragma unroll
            for (int d = 16; d > 0; d >>= 1)
                n2 = fmaxf(n2, __shfl_xor_sync(0xffffffffu, n2, d));
            if (threadIdx.x == 0)
                atomicMax(&g_kmax2[bh], __float_as_uint(n2));
        }
    } else {
        #pragma unroll
        for (int kk = 0; kk < 2; kk++) {
            int idx = threadIdx.y*32 + threadIdx.x + kk*256;
            int e = idx >> 4, lp = idx & 15;
            float v0 = tl[2*lp][e], v1 = tl[2*lp+1][e];
            uint32_t hp = pack_bf16x2(v0, v1);
            size_t o = ((size_t)bh*32 + e)*(SEQ/2) + (l0 >> 1) + lp;
            g_vph[o] = hp;
            g_vpl[o] = pack_bf16x2(v0 - bf_low(hp), v1 - bf_high(hp));
        }
    }
}

// ================= HMMA GEMM (bf16 3-term, double-buffered) =================
#define GBM 128
#define GBN 64
#define GBK 32
#define AKP (GBK/2)
#define APAD 20

__device__ __forceinline__ float gelu_exact(float x) {
    return 0.5f * x * (1.0f + erff(x * 0.70710678118654752440f));
}

__device__ __forceinline__ void epi2(float* C, size_t off, float c0, float c1,
                                     float2 bb, const float* res, int mode) {
    float2 o;
    if (mode == 1) {
        float2 r = *(const float2*)(res + off);
        o.x = (c0 + r.x)*0.5f; o.y = (c1 + r.y)*0.5f;
    } else if (mode == 2) {
        o.x = gelu_exact(c0 + bb.x); o.y = gelu_exact(c1 + bb.y);
    } else if (mode == 3) {
        float2 r = *(const float2*)(res + off);
        o.x = (c0 + bb.x + r.x)*0.5f; o.y = (c1 + bb.y + r.y)*0.5f;
    } else {
        o.x = c0; o.y = c1;
    }
    *(float2*)(C + off) = o;
}

extern __shared__ uint32_t dsm[];

__global__ __launch_bounds__(256, 2)
void gemm_mma(const float* __restrict__ A, const uint32_t* __restrict__ Bh,
              const uint32_t* __restrict__ Bl, const float* __restrict__ bias,
              const float* __restrict__ res, float* __restrict__ C,
              int M, int N, int K, int mode) {
    uint32_t* Ash = dsm;
    uint32_t* Bsh = dsm + 2*2*GBM*APAD;

    if (mode == 0) {
        int z = blockIdx.z;
        Bh += (size_t)z * DM * (DM/2);
        Bl += (size_t)z * DM * (DM/2);
        C  += (size_t)z * (size_t)M * N;
    }
    int bm = blockIdx.y * GBM;
    int bn = blockIdx.x * GBN;
    int tid = threadIdx.x;
    int warp = tid >> 5, lane = tid & 31;
    int g = lane >> 2, j = lane & 3;
    int wm = (warp & 3) * 32;
    int wn = (warp >> 2) * 32;
    int ldkp = K >> 1;

    int arow = tid >> 3;
    int akp0 = (tid & 7) * 2;
    int bn0  = tid >> 2;
    int bkp0 = (tid & 3) * 4;

    const float* ap[4];
    #pragma unroll
    for (int s = 0; s < 4; s++)
        ap[s] = A + (size_t)(bm + arow + 32*s)*K + (tid & 7)*4;
    const uint32_t* bph = Bh + (size_t)(bn + bn0)*ldkp + bkp0;
    const uint32_t* bpl = Bl + (size_t)(bn + bn0)*ldkp + bkp0;

    float acc[2][4][4];
    #pragma unroll
    for (int mt = 0; mt < 2; mt++)
        #pragma unroll
        for (int n = 0; n < 4; n++)
            #pragma unroll
            for (int r = 0; r < 4; r++) acc[mt][n][r] = 0.f;

    int nt = K / GBK;
    float4 af[4]; uint4 bfh, bfl;
    #pragma unroll
    for (int s = 0; s < 4; s++) af[s] = *(const float4*)ap[s];
    bfh = *(const uint4*)bph;
    bfl = *(const uint4*)bpl;

    {
        #pragma unroll
        for (int s = 0; s < 4; s++) {
            float4 v = af[s];
            uint32_t h0 = pack_bf16x2(v.x, v.y);
            uint32_t h1 = pack_bf16x2(v.z, v.w);
            uint32_t l0 = pack_bf16x2(v.x - bf_low(h0), v.y - bf_high(h0));
            uint32_t l1 = pack_bf16x2(v.z - bf_low(h1), v.w - bf_high(h1));
            int row = arow + 32*s;
            uint32_t* ph = Ash + row*APAD + akp0;
            uint32_t* pl = Ash + GBM*APAD + row*APAD + akp0;
            ph[0] = h0; ph[1] = h1; pl[0] = l0; pl[1] = l1;
        }
        uint32_t* ph = Bsh + bn0*APAD + bkp0;
        uint32_t* pl = Bsh + GBN*APAD + bn0*APAD + bkp0;
        ph[0]=bfh.x; ph[1]=bfh.y; ph[2]=bfh.z; ph[3]=bfh.w;
        pl[0]=bfl.x; pl[1]=bfl.y; pl[2]=bfl.z; pl[3]=bfl.w;
    }
    __syncthreads();

    for (int t = 0; t < nt; t++) {
        int buf = t & 1;
        if (t + 1 < nt) {
            int k0 = (t+1)*GBK;
            #pragma unroll
            for (int s = 0; s < 4; s++) af[s] = *(const float4*)(ap[s] + k0);
            bfh = *(const uint4*)(bph + (t+1)*AKP);
            bfl = *(const uint4*)(bpl + (t+1)*AKP);
        }

        const uint32_t* Ab = Ash + buf*2*GBM*APAD;
        const uint32_t* Bb = Bsh + buf*2*GBN*APAD;
        #pragma unroll
        for (int kc = 0; kc < 2; kc++) {
            uint32_t ah[2][4], al[2][4];
            #pragma unroll
            for (int mt = 0; mt < 2; mt++) {
                int r0 = wm + mt*16 + g;
                const uint32_t* pa  = Ab;
                const uint32_t* pal = Ab + GBM*APAD;
                ah[mt][0] = pa [(r0)  *APAD + kc*8 + j];
                ah[mt][1] = pa [(r0+8)*APAD + kc*8 + j];
                ah[mt][2] = pa [(r0)  *APAD + kc*8 + j + 4];
                ah[mt][3] = pa [(r0+8)*APAD + kc*8 + j + 4];
                al[mt][0] = pal[(r0)  *APAD + kc*8 + j];
                al[mt][1] = pal[(r0+8)*APAD + kc*8 + j];
                al[mt][2] = pal[(r0)  *APAD + kc*8 + j + 4];
                al[mt][3] = pal[(r0+8)*APAD + kc*8 + j + 4];
            }
            #pragma unroll
            for (int n = 0; n < 4; n++) {
                int c0 = wn + n*8 + g;
                uint32_t bh2[2], bl2[2];
                bh2[0] = Bb[c0*APAD + kc*8 + j];
                bh2[1] = Bb[c0*APAD + kc*8 + j + 4];
                bl2[0] = Bb[GBN*APAD + c0*APAD + kc*8 + j];
                bl2[1] = Bb[GBN*APAD + c0*APAD + kc*8 + j + 4];
                #pragma unroll
                for (int mt = 0; mt < 2; mt++) {
                    mma_bf16(acc[mt][n], ah[mt], bh2);
                    mma_bf16(acc[mt][n], al[mt], bh2);
                    mma_bf16(acc[mt][n], ah[mt], bl2);
                }
            }
        }

        if (t + 1 < nt) {
            int nb = buf ^ 1;
            uint32_t* An = Ash + nb*2*GBM*APAD;
            uint32_t* Bn = Bsh + nb*2*GBN*APAD;
            #pragma unroll
            for (int s = 0; s < 4; s++) {
                float4 v = af[s];
                uint32_t h0 = pack_bf16x2(v.x, v.y);
                uint32_t h1 = pack_bf16x2(v.z, v.w);
                uint32_t l0 = pack_bf16x2(v.x - bf_low(h0), v.y - bf_high(h0));
                uint32_t l1 = pack_bf16x2(v.z - bf_low(h1), v.w - bf_high(h1));
                int row = arow + 32*s;
                uint32_t* ph = An + row*APAD + akp0;
                uint32_t* pl = An + GBM*APAD + row*APAD + akp0;
                ph[0] = h0; ph[1] = h1; pl[0] = l0; pl[1] = l1;
            }
            uint32_t* ph = Bn + bn0*APAD + bkp0;
            uint32_t* pl = Bn + GBN*APAD + bn0*APAD + bkp0;
            ph[0]=bfh.x; ph[1]=bfh.y; ph[2]=bfh.z; ph[3]=bfh.w;
            pl[0]=bfl.x; pl[1]=bfl.y; pl[2]=bfl.z; pl[3]=bfl.w;
        }
        __syncthreads();
    }

    float2 bb[4];
    #pragma unroll
    for (int n = 0; n < 4; n++) {
        if (mode == 2 || mode == 3)
            bb[n] = *(const float2*)(bias + bn + wn + n*8 + 2*j);
        else
            bb[n] = make_float2(0.f, 0.f);
    }
    #pragma unroll
    for (int mt = 0; mt < 2; mt++) {
        int r0 = bm + wm + mt*16 + g;
        #pragma unroll
        for (int n = 0; n < 4; n++) {
            int col = bn + wn + n*8 + 2*j;
            size_t o0 = (size_t)r0*N + col;
            size_t o1 = (size_t)(r0 + 8)*N + col;
            epi2(C, o0, acc[mt][n][0], acc[mt][n][1], bb[n], res, mode);
            epi2(C, o1, acc[mt][n][2], acc[mt][n][3], bb[n], res, mode);
        }
    }
}

// ================= warp-MMA flash attention (static-bound softmax) ==========
#define KT  32
#define NIT (SEQ/KT)

__global__ __launch_bounds__(128, 3)
void attn_mma(const float* __restrict__ gq, const float* __restrict__ gmask,
              float* __restrict__ go) {
    __shared__ __align__(16) uint32_t Ksh[2][2][16][40];
    __shared__ __align__(16) uint32_t Vsh[2][2][32][20];
    __shared__ float sMask[2][KT];   // stores (1-mk)*NEGF

    int tid  = threadIdx.x;
    int warp = tid >> 5;
    int lane = tid & 31;
    int g    = lane >> 2;
    int j    = lane & 3;
    int bh   = blockIdx.y;
    int b    = bh >> 3, h = bh & 7;
    int q0   = blockIdx.x * 128 + warp * 32;

    uint32_t qh[2][2][4], ql[2][2][4];
    float qn2[2][2] = {};
    #pragma unroll
    for (int mt = 0; mt < 2; mt++) {
        #pragma unroll
        for (int rr = 0; rr < 2; rr++) {
            int row = q0 + mt*16 + g + rr*8;
            const float* qp = gq + ((size_t)b*SEQ + row)*DM + h*DH;
            #pragma unroll
            for (int u = 0; u < 4; u++) {
                float2 v = *(const float2*)(qp + u*8 + 2*j);
                qn2[mt][rr] = fmaf(v.x, v.x, fmaf(v.y, v.y, qn2[mt][rr]));
                uint32_t hp = pack_bf16x2(v.x, v.y);
                uint32_t lp = pack_bf16x2(v.x - bf_low(hp), v.y - bf_high(hp));
                qh[mt][u>>1][rr + 2*(u&1)] = hp;
                ql[mt][u>>1][rr + 2*(u&1)] = lp;
            }
        }
    }
    // reduce |q|^2 over the j-quad
    #pragma unroll
    for (int mt = 0; mt < 2; mt++)
        #pragma unroll
        for (int rr = 0; rr < 2; rr++) {
            qn2[mt][rr] += __shfl_xor_sync(0xffffffffu, qn2[mt][rr], 1);
            qn2[mt][rr] += __shfl_xor_sync(0xffffffffu, qn2[mt][rr], 2);
        }

    float kmaxn = sqrtf(__uint_as_float(g_kmax2[bh]));
    // per-row: fm = mq (0/1), cb = mq ? -(|q|*kmax - 30) : 0
    float fm[2][2], cb[2][2];
    #pragma unroll
    for (int mt = 0; mt < 2; mt++) {
        fm[mt][0] = gmask[b*SEQ + q0 + mt*16 + g];
        fm[mt][1] = gmask[b*SEQ + q0 + mt*16 + g + 8];
        #pragma unroll
        for (int rr = 0; rr < 2; rr++)
            cb[mt][rr] = (fm[mt][rr] == 0.f) ? 0.f
                       : -(sqrtf(qn2[mt][rr]) * kmaxn - 30.0f);
    }

    float lrow[2][2], ofr[2][4][4];
    #pragma unroll
    for (int mt = 0; mt < 2; mt++) {
        lrow[mt][0] = 0.f; lrow[mt][1] = 0.f;
        #pragma unroll
        for (int nd = 0; nd < 4; nd++)
            #pragma unroll
            for (int r = 0; r < 4; r++) ofr[mt][nd][r] = 0.f;
    }

    int kdp = tid >> 3;
    int kkg = (tid & 7) * 4;
    int vdm = tid >> 2;
    int vpg = (tid & 3) * 4;
    const uint32_t* kbh = g_kph + ((size_t)bh*16 + kdp)*SEQ + kkg;
    const uint32_t* kbl = g_kpl + ((size_t)bh*16 + kdp)*SEQ + kkg;
    const uint32_t* vbh = g_vph + ((size_t)bh*32 + vdm)*(SEQ/2) + vpg;
    const uint32_t* vbl = g_vpl + ((size_t)bh*32 + vdm)*(SEQ/2) + vpg;
    const float* mbase = gmask + b*SEQ + tid;

    uint4 rkh, rkl, rvh, rvl; float ml = 0.f;
    rkh = *(const uint4*)(kbh);
    rkl = *(const uint4*)(kbl);
    rvh = *(const uint4*)(vbh);
    rvl = *(const uint4*)(vbl);
    if (tid < KT) ml = *mbase;

    *(uint4*)&Ksh[0][0][kdp][kkg] = rkh;
    *(uint4*)&Ksh[0][1][kdp][kkg] = rkl;
    *(uint4*)&Vsh[0][0][vdm][vpg] = rvh;
    *(uint4*)&Vsh[0][1][vdm][vpg] = rvl;
    if (tid < KT) sMask[0][tid] = (1.0f - ml) * NEGF;
    __syncthreads();

    for (int it = 0; it < NIT; it++) {
        int bufc = it & 1;
        if (it + 1 < NIT) {
            rkh = *(const uint4*)(kbh + (it+1)*KT);
            rkl = *(const uint4*)(kbl + (it+1)*KT);
            rvh = *(const uint4*)(vbh + (it+1)*(KT/2));
            rvl = *(const uint4*)(vbl + (it+1)*(KT/2));
            if (tid < KT) ml = mbase[(it+1)*KT];
        }

        float sfr[2][4][4];
        #pragma unroll
        for (int mt = 0; mt < 2; mt++)
            #pragma unroll
            for (int n = 0; n < 4; n++)
                #pragma unroll
                for (int r = 0; r < 4; r++) sfr[mt][n][r] = 0.f;

        #pragma unroll
        for (int n = 0; n < 4; n++) {
            #pragma unroll
            for (int ks = 0; ks < 2; ks++) {
                uint32_t bhi[2], blo[2];
                bhi[0] = Ksh[bufc][0][ks*8 + j][n*8 + g];
                bhi[1] = Ksh[bufc][0][ks*8 + j + 4][n*8 + g];
                blo[0] = Ksh[bufc][1][ks*8 + j][n*8 + g];
                blo[1] = Ksh[bufc][1][ks*8 + j + 4][n*8 + g];
                #pragma unroll
                for (int mt = 0; mt < 2; mt++) {
                    mma_bf16(sfr[mt][n], qh[mt][ks], bhi);
                    mma_bf16(sfr[mt][n], ql[mt][ks], bhi);
                    mma_bf16(sfr[mt][n], qh[mt][ks], blo);
                }
            }
        }

        // ---- softmax, static bound: p = exp(fm*(s + maskneg) + cb) ----
        uint32_t phr0[2][4], phr1[2][4], plr0[2][4], plr1[2][4];
        #pragma unroll
        for (int mt = 0; mt < 2; mt++) {
            float f0 = fm[mt][0], f1 = fm[mt][1];
            float c0 = cb[mt][0], c1 = cb[mt][1];
            float ls0 = 0.f, ls1 = 0.f;
            #pragma unroll
            for (int n = 0; n < 4; n++) {
                float mk0 = sMask[bufc][n*8 + 2*j];
                float mk1 = sMask[bufc][n*8 + 2*j + 1];
                float p0 = __expf(fmaf(f0, sfr[mt][n][0] + mk0, c0));
                float p1 = __expf(fmaf(f0, sfr[mt][n][1] + mk1, c0));
                float p2 = __expf(fmaf(f1, sfr[mt][n][2] + mk0, c1));
                float p3 = __expf(fmaf(f1, sfr[mt][n][3] + mk1, c1));
                ls0 += p0 + p1; ls1 += p2 + p3;
                uint32_t h01 = pack_bf16x2(p0, p1);
                uint32_t h23 = pack_bf16x2(p2, p3);
                phr0[mt][n] = h01;
                phr1[mt][n] = h23;
                plr0[mt][n] = pack_bf16x2(p0 - bf_low(h01), p1 - bf_high(h01));
                plr1[mt][n] = pack_bf16x2(p2 - bf_low(h23), p3 - bf_high(h23));
            }
            lrow[mt][0] += ls0; lrow[mt][1] += ls1;
        }

        #pragma unroll
        for (int nd = 0; nd < 4; nd++) {
            #pragma unroll
            for (int k2 = 0; k2 < 2; k2++) {
                uint32_t bhi[2], blo[2];
                bhi[0] = Vsh[bufc][0][nd*8 + g][k2*8 + j];
                bhi[1] = Vsh[bufc][0][nd*8 + g][k2*8 + j + 4];
                blo[0] = Vsh[bufc][1][nd*8 + g][k2*8 + j];
                blo[1] = Vsh[bufc][1][nd*8 + g][k2*8 + j + 4];
                #pragma unroll
                for (int mt = 0; mt < 2; mt++) {
                    uint32_t ahi[4] = {phr0[mt][2*k2], phr1[mt][2*k2],
                                       phr0[mt][2*k2+1], phr1[mt][2*k2+1]};
                    uint32_t alo[4] = {plr0[mt][2*k2], plr1[mt][2*k2],
                                       plr0[mt][2*k2+1], plr1[mt][2*k2+1]};
                    mma_bf16(ofr[mt][nd], ahi, bhi);
                    mma_bf16(ofr[mt][nd], ahi, blo);
                    mma_bf16(ofr[mt][nd], alo, bhi);
                }
            }
        }

        if (it + 1 < NIT) {
            int bufn = bufc ^ 1;
            *(uint4*)&Ksh[bufn][0][kdp][kkg] = rkh;
            *(uint4*)&Ksh[bufn][1][kdp][kkg] = rkl;
            *(uint4*)&Vsh[bufn][0][vdm][vpg] = rvh;
            *(uint4*)&Vsh[bufn][1][vdm][vpg] = rvl;
            if (tid < KT) sMask[bufn][tid] = (1.0f - ml) * NEGF;
        }
        __syncthreads();
    }

    #pragma unroll
    for (int mt = 0; mt < 2; mt++) {
        float l0 = lrow[mt][0], l1 = lrow[mt][1];
        l0 += __shfl_xor_sync(0xffffffffu, l0, 1);
        l0 += __shfl_xor_sync(0xffffffffu, l0, 2);
        l1 += __shfl_xor_sync(0xffffffffu, l1, 1);
        l1 += __shfl_xor_sync(0xffffffffu, l1, 2);
        float inv0 = 1.0f / l0, inv1 = 1.0f / l1;
        int r0 = q0 + mt*16 + g;
        #pragma unroll
        for (int nd = 0; nd < 4; nd++) {
            int col = h*DH + nd*8 + 2*j;
            float2 v0 = make_float2(ofr[mt][nd][0]*inv0, ofr[mt][nd][1]*inv0);
            float2 v1 = make_float2(ofr[mt][nd][2]*inv1, ofr[mt][nd][3]*inv1);
            *(float2*)(go + ((size_t)b*SEQ + r0)*DM + col)     = v0;
            *(float2*)(go + ((size_t)b*SEQ + r0 + 8)*DM + col) = v1;
        }
    }
}

// ================= launch =================
extern "C" void kernel_launch(void* const* d_in, const int* in_sizes, int n_in,
                              void* d_out, int out_size) {
    const float* x    = (const float*)d_in[0];
    const float* mask = (const float*)d_in[1];
    const float* Wq   = (const float*)d_in[2];
    const float* Wk   = (const float*)d_in[3];
    const float* Wv   = (const float*)d_in[4];
    const float* Wo   = (const float*)d_in[5];
    const float* W1   = (const float*)d_in[6];
    const float* b1   = (const float*)d_in[7];
    const float* W2   = (const float*)d_in[8];
    const float* b2   = (const float*)d_in[9];
    float* out = (float*)d_out;

    float *qkv_p, *o_p, *xc_p, *ff_p;
    uint32_t *pqkh, *pqkl, *pwoh, *pwol, *pw1h, *pw1l, *pw2h, *pw2l;
    cudaGetSymbolAddress((void**)&qkv_p, g_qkv);
    cudaGetSymbolAddress((void**)&o_p,   g_obuf);
    cudaGetSymbolAddress((void**)&xc_p,  g_xc);
    cudaGetSymbolAddress((void**)&ff_p,  g_ff);
    cudaGetSymbolAddress((void**)&pqkh,  g_pwqkv_h);
    cudaGetSymbolAddress((void**)&pqkl,  g_pwqkv_l);
    cudaGetSymbolAddress((void**)&pwoh,  g_pwo_h);
    cudaGetSymbolAddress((void**)&pwol,  g_pwo_l);
    cudaGetSymbolAddress((void**)&pw1h,  g_pw1_h);
    cudaGetSymbolAddress((void**)&pw1l,  g_pw1_l);
    cudaGetSymbolAddress((void**)&pw2h,  g_pw2_h);
    cudaGetSymbolAddress((void**)&pw2l,  g_pw2_l);

    const int SMEM_GEMM = (2*2*GBM*APAD + 2*2*GBN*APAD) * 4;
    cudaFuncSetAttribute(gemm_mma, cudaFuncAttributeMaxDynamicSharedMemorySize, SMEM_GEMM);

    pack_qkv<<<(NL*3*DM*(DM/2) + 255)/256, 256>>>(Wq, Wk, Wv);
    pack_w<<<(NL*DM*(DM/2) + 255)/256, 256>>>(Wo, pwoh, pwol, DM, DM);
    pack_w<<<(NL*DF*(DM/2) + 255)/256, 256>>>(W1, pw1h, pw1l, DM, DF);
    pack_w<<<(NL*DM*(DF/2) + 255)/256, 256>>>(W2, pw2h, pw2l, DF, DM);

    const size_t QKV_STRIDE = (size_t)MR * DM;

    for (int n = 0; n < NL; n++) {
        const float* xin = (n == 0) ? x : xc_p;

        gemm_mma<<<dim3(DM/GBN, MR/GBM, 3), 256, SMEM_GEMM>>>(
            xin, pqkh + (size_t)n*3*DM*(DM/2), pqkl + (size_t)n*3*DM*(DM/2),
            nullptr, nullptr, qkv_p, MR, DM, DM, 0);

        reset_kmax<<<1, 32>>>();
        pack_kv<<<dim3(SEQ/32, NB*NH, 2), dim3(32, 8)>>>(
            qkv_p + QKV_STRIDE, qkv_p + 2*QKV_STRIDE);

        attn_mma<<<dim3(SEQ/128, NB*NH), 128>>>(qkv_p, mask, o_p);

        gemm_mma<<<dim3(DM/GBN, MR/GBM, 1), 256, SMEM_GEMM>>>(
            o_p, pwoh + (size_t)n*DM*(DM/2), pwol + (size_t)n*DM*(DM/2),
            nullptr, xin, xc_p, MR, DM, DM, 1);

        gemm_mma<<<dim3(DF/GBN, MR/GBM, 1), 256, SMEM_GEMM>>>(
            xc_p, pw1h + (size_t)n*DF*(DM/2), pw1l + (size_t)n*DF*(DM/2),
            b1 + (size_t)n*DF, nullptr, ff_p, MR, DF, DM, 2);

        float* dst = (n == NL - 1) ? out : xc_p;
        gemm_mma<<<dim3(DM/GBN, MR/GBM, 1), 256, SMEM_GEMM>>>(
            ff_p, pw2h + (size_t)n*DM*(DF/2), pw2l + (size_t)n*DM*(DF/2),
            b2 + (size_t)n*DM, xc_p, dst, MR, DM, DF, 3);
    }
}